// round 5
// baseline (speedup 1.0000x reference)
#include <cuda_runtime.h>
#include <cuda_bf16.h>
#include <math.h>
#include <stdint.h>

// Problem constants
#define VOCAB 50257
#define NPAD  50432              // 197 * 256
#define DMODEL 128
#define HID 256
#define BATCH 16
#define SEQ 128
#define GATES (3*HID)            // 768
#define MTOK (BATCH*SEQ)         // 2048
#define KCAT 768                 // concatenated K for 3-term split

// Scratch (__device__ globals per allocation-free rule)
__device__ float g_gx[MTOK * GATES];              // input-side gate projections
__device__ __nv_bfloat16 g_a2[MTOK * KCAT];       // [Ah | Ah | Al]
__device__ __nv_bfloat16 g_b2[NPAD * KCAT];       // [Bh | Bl | Bh]
__device__ unsigned int g_bar;                    // inter-CTA barrier counter
__device__ float g_hbuf[2][BATCH * HID];          // double-buffered h exchange [b][unit]

__device__ __forceinline__ uint32_t smem_to_u32(const void* p) {
    uint32_t a;
    asm("{ .reg .u64 t; cvta.to.shared.u64 t, %1; cvt.u32.u64 %0, t; }"
        : "=r"(a) : "l"(p));
    return a;
}

// ---------------------------------------------------------------------------
// Stage 1: tiled TN SGEMM with gather + bias (proven)
// ---------------------------------------------------------------------------
template<bool HAS_IDX, bool HAS_BIAS>
__global__ __launch_bounds__(256)
void gemm_tn(const float* __restrict__ A, const int* __restrict__ idx,
             const float* __restrict__ Bm, const float* __restrict__ bias,
             float* __restrict__ C, int M, int N, int K)
{
    constexpr int BM = 128, BN = 128, BK = 16;
    __shared__ float As[BK][BM];
    __shared__ float Bs[BK][BN];

    const int tid = threadIdx.x;
    const int tx = tid & 15, ty = tid >> 4;
    const int m0 = blockIdx.y * BM, n0 = blockIdx.x * BN;

    int a_row[2], a_col[2], b_row[2], b_col[2];
    const float* a_src[2];
    const float* b_src[2];
    bool b_ok[2];
#pragma unroll
    for (int i = 0; i < 2; i++) {
        int f = tid * 2 + i;
        int r = f >> 2, cv = (f & 3) * 4;
        a_row[i] = r; a_col[i] = cv;
        b_row[i] = r; b_col[i] = cv;
        int gm = m0 + r;
        int src_row = HAS_IDX ? idx[gm] : gm;
        a_src[i] = A + (size_t)src_row * K + cv;
        int gn = n0 + r;
        b_ok[i]  = (gn < N);
        b_src[i] = Bm + (size_t)(b_ok[i] ? gn : 0) * K + cv;
    }

    float acc[8][8];
#pragma unroll
    for (int i = 0; i < 8; i++)
#pragma unroll
        for (int j = 0; j < 8; j++) acc[i][j] = 0.f;

    const int ntiles = K / BK;
    float4 a_reg[2], b_reg[2];
#pragma unroll
    for (int i = 0; i < 2; i++) {
        a_reg[i] = *(const float4*)(a_src[i]);
        b_reg[i] = b_ok[i] ? *(const float4*)(b_src[i]) : make_float4(0.f,0.f,0.f,0.f);
    }

    for (int kt = 0; kt < ntiles; kt++) {
#pragma unroll
        for (int i = 0; i < 2; i++) {
            As[a_col[i]+0][a_row[i]] = a_reg[i].x;
            As[a_col[i]+1][a_row[i]] = a_reg[i].y;
            As[a_col[i]+2][a_row[i]] = a_reg[i].z;
            As[a_col[i]+3][a_row[i]] = a_reg[i].w;
            Bs[b_col[i]+0][b_row[i]] = b_reg[i].x;
            Bs[b_col[i]+1][b_row[i]] = b_reg[i].y;
            Bs[b_col[i]+2][b_row[i]] = b_reg[i].z;
            Bs[b_col[i]+3][b_row[i]] = b_reg[i].w;
        }
        __syncthreads();

        if (kt + 1 < ntiles) {
            int koff = (kt + 1) * BK;
#pragma unroll
            for (int i = 0; i < 2; i++) {
                a_reg[i] = *(const float4*)(a_src[i] + koff);
                b_reg[i] = b_ok[i] ? *(const float4*)(b_src[i] + koff)
                                   : make_float4(0.f,0.f,0.f,0.f);
            }
        }

#pragma unroll
        for (int k = 0; k < BK; k++) {
            float4 a0 = *(const float4*)&As[k][ty * 8];
            float4 a1 = *(const float4*)&As[k][ty * 8 + 4];
            float4 b0 = *(const float4*)&Bs[k][tx * 8];
            float4 b1 = *(const float4*)&Bs[k][tx * 8 + 4];
            float av[8] = {a0.x,a0.y,a0.z,a0.w,a1.x,a1.y,a1.z,a1.w};
            float bv[8] = {b0.x,b0.y,b0.z,b0.w,b1.x,b1.y,b1.z,b1.w};
#pragma unroll
            for (int i = 0; i < 8; i++)
#pragma unroll
                for (int j = 0; j < 8; j++)
                    acc[i][j] += av[i] * bv[j];
        }
        __syncthreads();
    }

#pragma unroll
    for (int i = 0; i < 8; i++) {
        int gm = m0 + ty * 8 + i;
        float* crow = C + (size_t)gm * N + n0 + tx * 8;
#pragma unroll
        for (int j = 0; j < 8; j++) {
            int gn = n0 + tx * 8 + j;
            if (gn < N) {
                float v = acc[i][j];
                if (HAS_BIAS) v += bias[gn];
                crow[j] = v;
            }
        }
    }
}

// ---------------------------------------------------------------------------
// Stage 2: multi-CTA GRU scan, v3. 64 CTAs; CTA c owns hidden units
// [4c, 4c+4) (12 W_hh rows in SMEM). H transposed [batch][unit] so W and H
// both stream as float4. One gpu-scope barrier per timestep.
// ---------------------------------------------------------------------------
#define NC 64
#define UPC 4                    // units per CTA
#define RPC 12                   // W rows per CTA (r,z,n gates of its units)
#define GRU_THREADS 192
#define WPAD 260                 // row stride (floats): 16B-aligned

__global__ __launch_bounds__(GRU_THREADS)
void gru_scan3(const float* __restrict__ gx, const float* __restrict__ Whh,
               const float* __restrict__ bhh, __nv_bfloat16* __restrict__ a2)
{
    __shared__ float W_sm[RPC][WPAD];
    __shared__ float H_sm[BATCH][WPAD];     // [batch][unit]
    __shared__ float gh_sm[RPC][17];

    const int cta = blockIdx.x;
    const int tid = threadIdx.x;
    const int rl  = tid >> 4;               // 0..11  local gate-row
    const int b   = tid & 15;               // batch

    auto grow_of = [&](int r) {
        return (r < UPC)     ? cta * UPC + r
             : (r < 2*UPC)   ? HID + cta * UPC + (r - UPC)
                             : 2 * HID + cta * UPC + (r - 2*UPC);
    };

    for (int i = tid; i < RPC * HID; i += GRU_THREADS) {
        int r = i / HID, k = i % HID;
        W_sm[r][k] = Whh[(size_t)grow_of(r) * HID + k];
    }
    const float bias = bhh[grow_of(rl)];
    for (int i = tid; i < BATCH * HID; i += GRU_THREADS)
        H_sm[i >> 8][i & 255] = 0.f;
    __syncthreads();

    const int u   = tid >> 4;               // update-unit (tid < 64)
    const int uid = cta * UPC + u;

    for (int t = 0; t < SEQ; t++) {
        // Prefetch gx operands for h-update (overlaps the dot)
        float xr = 0.f, xz = 0.f, xn = 0.f;
        if (tid < UPC * BATCH) {
            const float* gxr = gx + (size_t)(b * SEQ + t) * GATES;
            xr = gxr[uid]; xz = gxr[HID + uid]; xn = gxr[2 * HID + uid];
        }

        // gh[rl][b] = bias + dot(W_sm[rl], H_sm[b])  (float4 both sides)
        float s0 = bias, s1 = 0.f, s2 = 0.f, s3 = 0.f;
#pragma unroll 16
        for (int k = 0; k < HID; k += 4) {
            float4 w = *(const float4*)&W_sm[rl][k];
            float4 h = *(const float4*)&H_sm[b][k];
            s0 += w.x * h.x; s1 += w.y * h.y; s2 += w.z * h.z; s3 += w.w * h.w;
        }
        gh_sm[rl][b] = (s0 + s1) + (s2 + s3);
        __syncthreads();

        if (tid < UPC * BATCH) {
            float hr = gh_sm[u][b];
            float hz = gh_sm[UPC + u][b];
            float hn = gh_sm[2 * UPC + u][b];
            float hp = H_sm[b][uid];
            float r = 1.f / (1.f + expf(-(xr + hr)));
            float z = 1.f / (1.f + expf(-(xz + hz)));
            float n = tanhf(xn + r * hn);
            float hnew = (1.f - z) * n + z * hp;
            g_hbuf[t & 1][b * HID + uid] = hnew;
            size_t base = (size_t)(b * SEQ + t) * KCAT;
            __nv_bfloat16 hh = __float2bfloat16_rn(hnew);
            a2[base + uid]           = hh;
            a2[base + HID + uid]     = hh;
            a2[base + 2 * HID + uid] = __float2bfloat16_rn(hnew - __bfloat162float(hh));
        }
        __syncthreads();

        if (tid == 0) {
            __threadfence();
            atomicAdd(&g_bar, 1u);
            const unsigned tgt = (unsigned)NC * (t + 1);
            unsigned v;
            do {
                asm volatile("ld.acquire.gpu.u32 %0, [%1];"
                             : "=r"(v) : "l"(&g_bar) : "memory");
            } while (v < tgt);
        }
        __syncthreads();

        // refresh full H (float4)
        for (int i = tid; i < BATCH * HID / 4; i += GRU_THREADS) {
            int bb = i >> 6, k = (i & 63) * 4;
            *(float4*)&H_sm[bb][k] = *(const float4*)&g_hbuf[t & 1][bb * HID + k];
        }
        __syncthreads();
    }
}

// ---------------------------------------------------------------------------
// W_out -> B2 = [hi | lo | hi] bf16 rows (padded/zeroed to NPAD rows)
// ---------------------------------------------------------------------------
__global__ __launch_bounds__(256)
void conv_w2(const float* __restrict__ W, __nv_bfloat16* __restrict__ B2)
{
    int idx = blockIdx.x * blockDim.x + threadIdx.x;
    int v = idx >> 6;
    int k4 = (idx & 63) * 4;
    if (v >= NPAD) return;

    __nv_bfloat162 h01, h23, l01, l23;
    if (v < VOCAB) {
        float4 x = *(const float4*)(W + (size_t)v * HID + k4);
        __nv_bfloat16 h0 = __float2bfloat16_rn(x.x);
        __nv_bfloat16 h1 = __float2bfloat16_rn(x.y);
        __nv_bfloat16 h2 = __float2bfloat16_rn(x.z);
        __nv_bfloat16 h3 = __float2bfloat16_rn(x.w);
        h01 = __halves2bfloat162(h0, h1);
        h23 = __halves2bfloat162(h2, h3);
        l01 = __halves2bfloat162(__float2bfloat16_rn(x.x - __bfloat162float(h0)),
                                 __float2bfloat16_rn(x.y - __bfloat162float(h1)));
        l23 = __halves2bfloat162(__float2bfloat16_rn(x.z - __bfloat162float(h2)),
                                 __float2bfloat16_rn(x.w - __bfloat162float(h3)));
    } else {
        h01 = h23 = l01 = l23 = __halves2bfloat162(__float2bfloat16_rn(0.f),
                                                   __float2bfloat16_rn(0.f));
    }
    __nv_bfloat162* row = (__nv_bfloat162*)(B2 + (size_t)v * KCAT);
    row[(k4 >> 1)]                 = h01;  row[(k4 >> 1) + 1]                 = h23;
    row[(HID + k4) >> 1]           = l01;  row[((HID + k4) >> 1) + 1]         = l23;
    row[(2 * HID + k4) >> 1]       = h01;  row[((2 * HID + k4) >> 1) + 1]     = h23;
}

// ---------------------------------------------------------------------------
// Stage 3: LM head via HMMA bf16, K=768. CTA tile 128x256, 8 warps (2x4),
// warp tile 64x64, BK=64, cp.async 2-stage.
// ---------------------------------------------------------------------------
#define LM_BK 64
#define LM_NT (KCAT / LM_BK)           // 12
#define LM_A_B 16384                   // 128 rows * 128B
#define LM_B_B 32768                   // 256 rows * 128B
#define LM_STAGE_B (LM_A_B + LM_B_B)   // 49152
#define LM_SMEM (2 * LM_STAGE_B)       // 98304

__device__ __forceinline__ void cp16(uint32_t saddr, const void* gaddr) {
    asm volatile("cp.async.cg.shared.global [%0], [%1], 16;"
                 :: "r"(saddr), "l"(gaddr));
}

__global__ __launch_bounds__(256, 1)
void lm_head_hmma(const __nv_bfloat16* __restrict__ A2,
                  const __nv_bfloat16* __restrict__ B2,
                  float* __restrict__ out)
{
    extern __shared__ char smem[];
    const uint32_t sbase = smem_to_u32(smem);

    const int tid = threadIdx.x;
    const int lane = tid & 31;
    const int wid = tid >> 5;
    const int m0 = blockIdx.x * 128;
    const int n0 = blockIdx.y * 256;
    const int wm = (wid & 1) * 64;
    const int wn = (wid >> 1) * 64;

    const int lg = lane >> 3, lr = lane & 7;
    const int row16 = ((lg & 1) << 3) + lr;
    const int csel  = lg >> 1;

    float acc[4][8][4];
#pragma unroll
    for (int i = 0; i < 4; i++)
#pragma unroll
        for (int j = 0; j < 8; j++)
#pragma unroll
            for (int k = 0; k < 4; k++) acc[i][j][k] = 0.f;

    auto issue = [&](int kt) {
        const uint32_t stage = sbase + (kt & 1) * LM_STAGE_B;
#pragma unroll
        for (int i = 0; i < 4; i++) {        // A: 1024 chunks
            int q = i * 256 + tid;
            int row = q >> 3, c = q & 7;
            uint32_t soff = row * 128 + (((uint32_t)(c ^ (row & 7))) << 4);
            cp16(stage + soff,
                 A2 + (size_t)(m0 + row) * KCAT + kt * LM_BK + c * 8);
        }
#pragma unroll
        for (int i = 0; i < 8; i++) {        // B: 2048 chunks
            int q = i * 256 + tid;
            int row = q >> 3, c = q & 7;
            uint32_t soff = row * 128 + (((uint32_t)(c ^ (row & 7))) << 4);
            cp16(stage + LM_A_B + soff,
                 B2 + (size_t)(n0 + row) * KCAT + kt * LM_BK + c * 8);
        }
        asm volatile("cp.async.commit_group;" ::: "memory");
    };

    issue(0);

    for (int kt = 0; kt < LM_NT; kt++) {
        if (kt + 1 < LM_NT) {
            issue(kt + 1);
            asm volatile("cp.async.wait_group 1;" ::: "memory");
        } else {
            asm volatile("cp.async.wait_group 0;" ::: "memory");
        }
        __syncthreads();

        const uint32_t Ab = sbase + (kt & 1) * LM_STAGE_B;
        const uint32_t Bb = Ab + LM_A_B;

#pragma unroll
        for (int ks = 0; ks < 4; ks++) {
            const int kc = ks * 2;
            uint32_t a[4][4];
#pragma unroll
            for (int mt = 0; mt < 4; mt++) {
                int row = wm + mt * 16 + row16;
                uint32_t addr = Ab + row * 128 +
                    (((uint32_t)((kc + csel) ^ (row & 7))) << 4);
                asm volatile(
                    "ldmatrix.sync.aligned.m8n8.x4.shared.b16 {%0,%1,%2,%3}, [%4];"
                    : "=r"(a[mt][0]), "=r"(a[mt][1]), "=r"(a[mt][2]), "=r"(a[mt][3])
                    : "r"(addr));
            }
            uint32_t bf[8][2];
#pragma unroll
            for (int np = 0; np < 4; np++) {
                int row = wn + np * 16 + row16;
                uint32_t addr = Bb + row * 128 +
                    (((uint32_t)((kc + csel) ^ (row & 7))) << 4);
                uint32_t q0, q1, q2, q3;
                asm volatile(
                    "ldmatrix.sync.aligned.m8n8.x4.shared.b16 {%0,%1,%2,%3}, [%4];"
                    : "=r"(q0), "=r"(q1), "=r"(q2), "=r"(q3)
                    : "r"(addr));
                bf[np * 2][0] = q0;     bf[np * 2][1] = q2;
                bf[np * 2 + 1][0] = q1; bf[np * 2 + 1][1] = q3;
            }
#pragma unroll
            for (int mt = 0; mt < 4; mt++)
#pragma unroll
                for (int nt = 0; nt < 8; nt++) {
                    asm volatile(
                        "mma.sync.aligned.m16n8k16.row.col.f32.bf16.bf16.f32 "
                        "{%0,%1,%2,%3}, {%4,%5,%6,%7}, {%8,%9}, {%0,%1,%2,%3};"
                        : "+f"(acc[mt][nt][0]), "+f"(acc[mt][nt][1]),
                          "+f"(acc[mt][nt][2]), "+f"(acc[mt][nt][3])
                        : "r"(a[mt][0]), "r"(a[mt][1]), "r"(a[mt][2]), "r"(a[mt][3]),
                          "r"(bf[nt][0]), "r"(bf[nt][1]));
                }
        }
        __syncthreads();
    }

    const int elr = lane >> 2;
    const int elc = (lane & 3) * 2;
    const bool full = (n0 + 256 <= VOCAB);
#pragma unroll
    for (int mt = 0; mt < 4; mt++) {
#pragma unroll
        for (int nt = 0; nt < 8; nt++) {
            int gr = m0 + wm + mt * 16 + elr;
            int gc = n0 + wn + nt * 8 + elc;
            float* p0 = out + (size_t)gr * VOCAB + gc;
            float* p1 = out + (size_t)(gr + 8) * VOCAB + gc;
            if (full) {
                p0[0] = acc[mt][nt][0]; p0[1] = acc[mt][nt][1];
                p1[0] = acc[mt][nt][2]; p1[1] = acc[mt][nt][3];
            } else {
                if (gc < VOCAB)     { p0[0] = acc[mt][nt][0]; p1[0] = acc[mt][nt][2]; }
                if (gc + 1 < VOCAB) { p0[1] = acc[mt][nt][1]; p1[1] = acc[mt][nt][3]; }
            }
        }
    }
}

// ---------------------------------------------------------------------------
// Launch
// ---------------------------------------------------------------------------
extern "C" void kernel_launch(void* const* d_in, const int* in_sizes, int n_in,
                              void* d_out, int out_size)
{
    const int*   ids   = (const int*)  d_in[0];
    const float* embed = (const float*)d_in[1];
    const float* W_ih  = (const float*)d_in[2];
    const float* b_ih  = (const float*)d_in[3];
    const float* W_hh  = (const float*)d_in[4];
    const float* b_hh  = (const float*)d_in[5];
    const float* W_out = (const float*)d_in[6];
    float* out = (float*)d_out;

    float* gx_ptr;
    __nv_bfloat16 *a2_ptr, *b2_ptr;
    void* bar_ptr;
    cudaGetSymbolAddress((void**)&gx_ptr, g_gx);
    cudaGetSymbolAddress((void**)&a2_ptr, g_a2);
    cudaGetSymbolAddress((void**)&b2_ptr, g_b2);
    cudaGetSymbolAddress(&bar_ptr, g_bar);

    cudaFuncSetAttribute(lm_head_hmma,
                         cudaFuncAttributeMaxDynamicSharedMemorySize, LM_SMEM);

    cudaMemsetAsync(bar_ptr, 0, sizeof(unsigned int));

    // 0) B2 = [hi | lo | hi] split of W_out
    {
        int nthreads = NPAD * 64;
        conv_w2<<<(nthreads + 255) / 256, 256>>>(W_out, b2_ptr);
    }

    // 1) gx = embed[ids] @ W_ih^T + b_ih
    {
        dim3 grid(GATES / 128, MTOK / 128);
        gemm_tn<true, true><<<grid, 256>>>(embed, ids, W_ih, b_ih,
                                           gx_ptr, MTOK, GATES, DMODEL);
    }

    // 2) multi-CTA GRU scan v3
    gru_scan3<<<NC, GRU_THREADS>>>(gx_ptr, W_hh, b_hh, a2_ptr);

    // 3) LM head on HMMA tensor cores
    {
        dim3 grid(MTOK / 128, NPAD / 256);
        lm_head_hmma<<<grid, 256, LM_SMEM>>>(a2_ptr, b2_ptr, out);
    }
}

// round 6
// speedup vs baseline: 1.1819x; 1.1819x over previous
#include <cuda_runtime.h>
#include <cuda_bf16.h>
#include <math.h>
#include <stdint.h>

// Problem constants
#define VOCAB 50257
#define NPAD  50304              // 393 * 128
#define DMODEL 128
#define HID 256
#define BATCH 16
#define SEQ 128
#define GATES (3*HID)            // 768
#define MTOK (BATCH*SEQ)         // 2048
#define KCAT 768                 // concatenated K for 3-term split

// Scratch (__device__ globals per allocation-free rule)
__device__ float g_gx[MTOK * GATES];              // input-side gate projections
__device__ __nv_bfloat16 g_a2[MTOK * KCAT];       // [Ah | Ah | Al]
__device__ __nv_bfloat16 g_b2[NPAD * KCAT];       // [Bh | Bl | Bh]
__device__ float g_hbuf[2][BATCH * HID];          // double-buffered h exchange
__device__ int g_flags[4][64];                    // per-group CTA arrival flags

__device__ __forceinline__ uint32_t smem_to_u32(const void* p) {
    uint32_t a;
    asm("{ .reg .u64 t; cvta.to.shared.u64 t, %1; cvt.u32.u64 %0, t; }"
        : "=r"(a) : "l"(p));
    return a;
}

// ---------------------------------------------------------------------------
// Stage 1: tiled TN SGEMM with gather + bias (proven)
// ---------------------------------------------------------------------------
template<bool HAS_IDX, bool HAS_BIAS>
__global__ __launch_bounds__(256)
void gemm_tn(const float* __restrict__ A, const int* __restrict__ idx,
             const float* __restrict__ Bm, const float* __restrict__ bias,
             float* __restrict__ C, int M, int N, int K)
{
    constexpr int BM = 128, BN = 128, BK = 16;
    __shared__ float As[BK][BM];
    __shared__ float Bs[BK][BN];

    const int tid = threadIdx.x;
    const int tx = tid & 15, ty = tid >> 4;
    const int m0 = blockIdx.y * BM, n0 = blockIdx.x * BN;

    int a_row[2], a_col[2], b_row[2], b_col[2];
    const float* a_src[2];
    const float* b_src[2];
    bool b_ok[2];
#pragma unroll
    for (int i = 0; i < 2; i++) {
        int f = tid * 2 + i;
        int r = f >> 2, cv = (f & 3) * 4;
        a_row[i] = r; a_col[i] = cv;
        b_row[i] = r; b_col[i] = cv;
        int gm = m0 + r;
        int src_row = HAS_IDX ? idx[gm] : gm;
        a_src[i] = A + (size_t)src_row * K + cv;
        int gn = n0 + r;
        b_ok[i]  = (gn < N);
        b_src[i] = Bm + (size_t)(b_ok[i] ? gn : 0) * K + cv;
    }

    float acc[8][8];
#pragma unroll
    for (int i = 0; i < 8; i++)
#pragma unroll
        for (int j = 0; j < 8; j++) acc[i][j] = 0.f;

    const int ntiles = K / BK;
    float4 a_reg[2], b_reg[2];
#pragma unroll
    for (int i = 0; i < 2; i++) {
        a_reg[i] = *(const float4*)(a_src[i]);
        b_reg[i] = b_ok[i] ? *(const float4*)(b_src[i]) : make_float4(0.f,0.f,0.f,0.f);
    }

    for (int kt = 0; kt < ntiles; kt++) {
#pragma unroll
        for (int i = 0; i < 2; i++) {
            As[a_col[i]+0][a_row[i]] = a_reg[i].x;
            As[a_col[i]+1][a_row[i]] = a_reg[i].y;
            As[a_col[i]+2][a_row[i]] = a_reg[i].z;
            As[a_col[i]+3][a_row[i]] = a_reg[i].w;
            Bs[b_col[i]+0][b_row[i]] = b_reg[i].x;
            Bs[b_col[i]+1][b_row[i]] = b_reg[i].y;
            Bs[b_col[i]+2][b_row[i]] = b_reg[i].z;
            Bs[b_col[i]+3][b_row[i]] = b_reg[i].w;
        }
        __syncthreads();

        if (kt + 1 < ntiles) {
            int koff = (kt + 1) * BK;
#pragma unroll
            for (int i = 0; i < 2; i++) {
                a_reg[i] = *(const float4*)(a_src[i] + koff);
                b_reg[i] = b_ok[i] ? *(const float4*)(b_src[i] + koff)
                                   : make_float4(0.f,0.f,0.f,0.f);
            }
        }

#pragma unroll
        for (int k = 0; k < BK; k++) {
            float4 a0 = *(const float4*)&As[k][ty * 8];
            float4 a1 = *(const float4*)&As[k][ty * 8 + 4];
            float4 b0 = *(const float4*)&Bs[k][tx * 8];
            float4 b1 = *(const float4*)&Bs[k][tx * 8 + 4];
            float av[8] = {a0.x,a0.y,a0.z,a0.w,a1.x,a1.y,a1.z,a1.w};
            float bv[8] = {b0.x,b0.y,b0.z,b0.w,b1.x,b1.y,b1.z,b1.w};
#pragma unroll
            for (int i = 0; i < 8; i++)
#pragma unroll
                for (int j = 0; j < 8; j++)
                    acc[i][j] += av[i] * bv[j];
        }
        __syncthreads();
    }

#pragma unroll
    for (int i = 0; i < 8; i++) {
        int gm = m0 + ty * 8 + i;
        float* crow = C + (size_t)gm * N + n0 + tx * 8;
#pragma unroll
        for (int j = 0; j < 8; j++) {
            int gn = n0 + tx * 8 + j;
            if (gn < N) {
                float v = acc[i][j];
                if (HAS_BIAS) v += bias[gn];
                crow[j] = v;
            }
        }
    }
}

// ---------------------------------------------------------------------------
// Stage 2: GRU scan v4. 4 independent groups x 32 CTAs. Group g owns batches
// [4g,4g+4). CTA c in group owns units [8c,8c+8) (24 W rows, register-
// resident, k-split 4 ways). Flag-based release/acquire barrier per group.
// ---------------------------------------------------------------------------
#define NBG 4                    // batches per group
#define GUPC 8                   // units per CTA
#define GRU_T 384
#define CH 68                    // chunk stride (floats), conflict-free

__global__ __launch_bounds__(GRU_T)
void gru_scan4(const float* __restrict__ gx, const float* __restrict__ Whh,
               const float* __restrict__ bhh, __nv_bfloat16* __restrict__ a2)
{
    __shared__ float H_sm[16 * CH];       // [b*4+c][68] chunks of H
    __shared__ float gh_sm[24][8];

    const int cta = blockIdx.x & 31;      // CTA within group
    const int grp = blockIdx.x >> 5;
    const int tid = threadIdx.x;
    const int c    = tid & 3;             // k-chunk 0..3
    const int pair = tid >> 2;            // 0..95
    const int rl   = pair >> 2;           // 0..23 local gate-row
    const int b    = pair & 3;            // local batch
    const int cta8 = cta * GUPC;

    const int grow = (rl < 8)  ? cta8 + rl
                   : (rl < 16) ? HID + cta8 + (rl - 8)
                               : 2 * HID + cta8 + (rl - 16);

    // W chunk (64 floats) into registers
    float w[64];
    {
        const float4* src = (const float4*)(Whh + (size_t)grow * HID + c * 64);
#pragma unroll
        for (int i = 0; i < 16; i++) {
            float4 v = src[i];
            w[4*i] = v.x; w[4*i+1] = v.y; w[4*i+2] = v.z; w[4*i+3] = v.w;
        }
    }

    // h-update role (threads 0..31): unit uu, batch ub
    const int uu = tid >> 2;
    const int ub = tid & 3;
    const int uid = cta8 + uu;
    const int ubglob = grp * NBG + ub;
    float bias_r = 0.f, bias_z = 0.f, bias_n = 0.f;
    if (tid < 32) {
        bias_r = bhh[uid];
        bias_z = bhh[HID + uid];
        bias_n = bhh[2 * HID + uid];
    }

    for (int i = tid; i < 16 * CH; i += GRU_T) H_sm[i] = 0.f;
    __syncthreads();

    for (int t = 0; t < SEQ; t++) {
        // prefetch gx operands (overlap with dot)
        float xr = 0.f, xz = 0.f, xn = 0.f;
        if (tid < 32) {
            const float* p = gx + (size_t)(ubglob * SEQ + t) * GATES;
            xr = p[uid]; xz = p[HID + uid]; xn = p[2 * HID + uid];
        }

        // partial dot over k-chunk c
        const float* hB = &H_sm[(b * 4 + c) * CH];
        float s0 = 0.f, s1 = 0.f, s2 = 0.f, s3 = 0.f;
#pragma unroll
        for (int i = 0; i < 16; i++) {
            float4 h = *(const float4*)&hB[4 * i];
            s0 += w[4*i]   * h.x; s1 += w[4*i+1] * h.y;
            s2 += w[4*i+2] * h.z; s3 += w[4*i+3] * h.w;
        }
        float s = (s0 + s1) + (s2 + s3);
        s += __shfl_down_sync(0xffffffffu, s, 1, 4);
        s += __shfl_down_sync(0xffffffffu, s, 2, 4);
        if (c == 0) gh_sm[rl][b] = s;
        __syncthreads();

        if (tid < 32) {
            float hr = gh_sm[uu][ub]      + bias_r;
            float hz = gh_sm[8 + uu][ub]  + bias_z;
            float hn = gh_sm[16 + uu][ub] + bias_n;
            float hp = H_sm[(ub * 4 + (uid >> 6)) * CH + (uid & 63)];
            float r = 1.f / (1.f + expf(-(xr + hr)));
            float z = 1.f / (1.f + expf(-(xz + hz)));
            float n = tanhf(xn + r * hn);
            float hnew = (1.f - z) * n + z * hp;
            g_hbuf[t & 1][ubglob * HID + uid] = hnew;
            size_t base = (size_t)(ubglob * SEQ + t) * KCAT;
            __nv_bfloat16 hh = __float2bfloat16_rn(hnew);
            a2[base + uid]           = hh;
            a2[base + HID + uid]     = hh;
            a2[base + 2 * HID + uid] = __float2bfloat16_rn(hnew - __bfloat162float(hh));
        }
        __syncthreads();

        // group barrier: one release store per CTA, warp-0 lanes each poll one flag
        if (tid == 0) {
            asm volatile("st.release.gpu.u32 [%0], %1;"
                         :: "l"(&g_flags[grp][cta]), "r"(t + 1) : "memory");
        }
        if (tid < 32) {
            int v;
            do {
                asm volatile("ld.acquire.gpu.u32 %0, [%1];"
                             : "=r"(v) : "l"(&g_flags[grp][tid]) : "memory");
            } while (v < t + 1);
        }
        __syncthreads();

        // refresh group's H (L2-coherent loads)
        if (tid < 256) {
            int bb = tid >> 6, k4 = (tid & 63) * 4;
            const float4* src = (const float4*)&g_hbuf[t & 1][(grp * NBG + bb) * HID + k4];
            float4 v;
            asm volatile("ld.global.cg.v4.f32 {%0,%1,%2,%3}, [%4];"
                         : "=f"(v.x), "=f"(v.y), "=f"(v.z), "=f"(v.w) : "l"(src));
            float* d = &H_sm[(bb * 4 + (k4 >> 6)) * CH + (k4 & 63)];
            d[0] = v.x; d[1] = v.y; d[2] = v.z; d[3] = v.w;
        }
        __syncthreads();
    }
}

// ---------------------------------------------------------------------------
// W_out -> B2 = [hi | lo | hi] bf16 rows (padded/zeroed to NPAD rows)
// ---------------------------------------------------------------------------
__global__ __launch_bounds__(256)
void conv_w2(const float* __restrict__ W, __nv_bfloat16* __restrict__ B2)
{
    int idx = blockIdx.x * blockDim.x + threadIdx.x;
    int v = idx >> 6;
    int k4 = (idx & 63) * 4;
    if (v >= NPAD) return;

    __nv_bfloat162 h01, h23, l01, l23;
    if (v < VOCAB) {
        float4 x = *(const float4*)(W + (size_t)v * HID + k4);
        __nv_bfloat16 h0 = __float2bfloat16_rn(x.x);
        __nv_bfloat16 h1 = __float2bfloat16_rn(x.y);
        __nv_bfloat16 h2 = __float2bfloat16_rn(x.z);
        __nv_bfloat16 h3 = __float2bfloat16_rn(x.w);
        h01 = __halves2bfloat162(h0, h1);
        h23 = __halves2bfloat162(h2, h3);
        l01 = __halves2bfloat162(__float2bfloat16_rn(x.x - __bfloat162float(h0)),
                                 __float2bfloat16_rn(x.y - __bfloat162float(h1)));
        l23 = __halves2bfloat162(__float2bfloat16_rn(x.z - __bfloat162float(h2)),
                                 __float2bfloat16_rn(x.w - __bfloat162float(h3)));
    } else {
        h01 = h23 = l01 = l23 = __halves2bfloat162(__float2bfloat16_rn(0.f),
                                                   __float2bfloat16_rn(0.f));
    }
    __nv_bfloat162* row = (__nv_bfloat162*)(B2 + (size_t)v * KCAT);
    row[(k4 >> 1)]                 = h01;  row[(k4 >> 1) + 1]                 = h23;
    row[(HID + k4) >> 1]           = l01;  row[((HID + k4) >> 1) + 1]         = l23;
    row[(2 * HID + k4) >> 1]       = h01;  row[((2 * HID + k4) >> 1) + 1]     = h23;
}

// ---------------------------------------------------------------------------
// Stage 3: LM head via HMMA bf16, K=768. CTA 128x128, 8 warps (2x4),
// warp tile 64x32, BK=64, cp.async 2-stage, B-fragment double buffering.
// ---------------------------------------------------------------------------
#define LM_BK 64
#define LM_NT (KCAT / LM_BK)          // 12
#define LM_TILE_B 16384               // 128 rows * 128B
#define LM_STAGE_B (2 * LM_TILE_B)
#define LM_SMEM (2 * LM_STAGE_B)      // 65536

__device__ __forceinline__ void cp16(uint32_t saddr, const void* gaddr) {
    asm volatile("cp.async.cg.shared.global [%0], [%1], 16;"
                 :: "r"(saddr), "l"(gaddr));
}

__global__ __launch_bounds__(256, 2)
void lm_head_hmma(const __nv_bfloat16* __restrict__ A2,
                  const __nv_bfloat16* __restrict__ B2,
                  float* __restrict__ out)
{
    extern __shared__ char smem[];
    const uint32_t sbase = smem_to_u32(smem);

    const int tid = threadIdx.x;
    const int lane = tid & 31;
    const int wid = tid >> 5;
    const int m0 = blockIdx.x * 128;
    const int n0 = blockIdx.y * 128;
    const int wm = (wid >> 2) * 64;
    const int wn = (wid & 3) * 32;

    const int lg = lane >> 3, lr = lane & 7;
    const int row16 = ((lg & 1) << 3) + lr;
    const int csel  = lg >> 1;

    float acc[4][4][4];
#pragma unroll
    for (int i = 0; i < 4; i++)
#pragma unroll
        for (int j = 0; j < 4; j++)
#pragma unroll
            for (int k = 0; k < 4; k++) acc[i][j][k] = 0.f;

    auto issue = [&](int kt) {
        const uint32_t stage = sbase + (kt & 1) * LM_STAGE_B;
#pragma unroll
        for (int i = 0; i < 4; i++) {
            int q = i * 256 + tid;
            int row = q >> 3, c = q & 7;
            uint32_t soff = row * 128 + (((uint32_t)(c ^ (row & 7))) << 4);
            cp16(stage + soff,
                 A2 + (size_t)(m0 + row) * KCAT + kt * LM_BK + c * 8);
            cp16(stage + LM_TILE_B + soff,
                 B2 + (size_t)(n0 + row) * KCAT + kt * LM_BK + c * 8);
        }
        asm volatile("cp.async.commit_group;" ::: "memory");
    };

    // B-fragment loader (double buffered)
    uint32_t bfr[2][4][2];
    auto loadB = [&](uint32_t Bb, int ks, int buf) {
        const int kc = ks * 2;
#pragma unroll
        for (int np = 0; np < 2; np++) {
            int row = wn + np * 16 + row16;
            uint32_t addr = Bb + row * 128 +
                (((uint32_t)((kc + csel) ^ (row & 7))) << 4);
            uint32_t q0, q1, q2, q3;
            asm volatile(
                "ldmatrix.sync.aligned.m8n8.x4.shared.b16 {%0,%1,%2,%3}, [%4];"
                : "=r"(q0), "=r"(q1), "=r"(q2), "=r"(q3)
                : "r"(addr));
            bfr[buf][np * 2][0] = q0;     bfr[buf][np * 2][1] = q2;
            bfr[buf][np * 2 + 1][0] = q1; bfr[buf][np * 2 + 1][1] = q3;
        }
    };

    issue(0);

    for (int kt = 0; kt < LM_NT; kt++) {
        if (kt + 1 < LM_NT) {
            issue(kt + 1);
            asm volatile("cp.async.wait_group 1;" ::: "memory");
        } else {
            asm volatile("cp.async.wait_group 0;" ::: "memory");
        }
        __syncthreads();

        const uint32_t Ab = sbase + (kt & 1) * LM_STAGE_B;
        const uint32_t Bb = Ab + LM_TILE_B;

        loadB(Bb, 0, 0);

#pragma unroll
        for (int ks = 0; ks < 4; ks++) {
            const int kc = ks * 2;
            uint32_t a[4][4];
#pragma unroll
            for (int mt = 0; mt < 4; mt++) {
                int row = wm + mt * 16 + row16;
                uint32_t addr = Ab + row * 128 +
                    (((uint32_t)((kc + csel) ^ (row & 7))) << 4);
                asm volatile(
                    "ldmatrix.sync.aligned.m8n8.x4.shared.b16 {%0,%1,%2,%3}, [%4];"
                    : "=r"(a[mt][0]), "=r"(a[mt][1]), "=r"(a[mt][2]), "=r"(a[mt][3])
                    : "r"(addr));
            }
            if (ks < 3) loadB(Bb, ks + 1, (ks + 1) & 1);

            const int cur = ks & 1;
#pragma unroll
            for (int mt = 0; mt < 4; mt++)
#pragma unroll
                for (int nt = 0; nt < 4; nt++) {
                    asm volatile(
                        "mma.sync.aligned.m16n8k16.row.col.f32.bf16.bf16.f32 "
                        "{%0,%1,%2,%3}, {%4,%5,%6,%7}, {%8,%9}, {%0,%1,%2,%3};"
                        : "+f"(acc[mt][nt][0]), "+f"(acc[mt][nt][1]),
                          "+f"(acc[mt][nt][2]), "+f"(acc[mt][nt][3])
                        : "r"(a[mt][0]), "r"(a[mt][1]), "r"(a[mt][2]), "r"(a[mt][3]),
                          "r"(bfr[cur][nt][0]), "r"(bfr[cur][nt][1]));
                }
        }
        __syncthreads();
    }

    const int elr = lane >> 2;
    const int elc = (lane & 3) * 2;
    const bool full = (n0 + 128 <= VOCAB);
#pragma unroll
    for (int mt = 0; mt < 4; mt++) {
#pragma unroll
        for (int nt = 0; nt < 4; nt++) {
            int gr = m0 + wm + mt * 16 + elr;
            int gc = n0 + wn + nt * 8 + elc;
            float* p0 = out + (size_t)gr * VOCAB + gc;
            float* p1 = out + (size_t)(gr + 8) * VOCAB + gc;
            if (full) {
                p0[0] = acc[mt][nt][0]; p0[1] = acc[mt][nt][1];
                p1[0] = acc[mt][nt][2]; p1[1] = acc[mt][nt][3];
            } else {
                if (gc < VOCAB)     { p0[0] = acc[mt][nt][0]; p1[0] = acc[mt][nt][2]; }
                if (gc + 1 < VOCAB) { p0[1] = acc[mt][nt][1]; p1[1] = acc[mt][nt][3]; }
            }
        }
    }
}

// ---------------------------------------------------------------------------
// Launch
// ---------------------------------------------------------------------------
extern "C" void kernel_launch(void* const* d_in, const int* in_sizes, int n_in,
                              void* d_out, int out_size)
{
    const int*   ids   = (const int*)  d_in[0];
    const float* embed = (const float*)d_in[1];
    const float* W_ih  = (const float*)d_in[2];
    const float* b_ih  = (const float*)d_in[3];
    const float* W_hh  = (const float*)d_in[4];
    const float* b_hh  = (const float*)d_in[5];
    const float* W_out = (const float*)d_in[6];
    float* out = (float*)d_out;

    float* gx_ptr;
    __nv_bfloat16 *a2_ptr, *b2_ptr;
    void* flags_ptr;
    cudaGetSymbolAddress((void**)&gx_ptr, g_gx);
    cudaGetSymbolAddress((void**)&a2_ptr, g_a2);
    cudaGetSymbolAddress((void**)&b2_ptr, g_b2);
    cudaGetSymbolAddress(&flags_ptr, g_flags);

    cudaFuncSetAttribute(lm_head_hmma,
                         cudaFuncAttributeMaxDynamicSharedMemorySize, LM_SMEM);

    // reset barrier flags (graph-capturable memset node)
    cudaMemsetAsync(flags_ptr, 0, sizeof(int) * 4 * 64);

    // 0) B2 = [hi | lo | hi] split of W_out
    {
        int nthreads = NPAD * 64;
        conv_w2<<<(nthreads + 255) / 256, 256>>>(W_out, b2_ptr);
    }

    // 1) gx = embed[ids] @ W_ih^T + b_ih
    {
        dim3 grid(GATES / 128, MTOK / 128);
        gemm_tn<true, true><<<grid, 256>>>(embed, ids, W_ih, b_ih,
                                           gx_ptr, MTOK, GATES, DMODEL);
    }

    // 2) GRU scan v4 (4 groups x 32 CTAs)
    gru_scan4<<<128, GRU_T>>>(gx_ptr, W_hh, b_hh, a2_ptr);

    // 3) LM head on HMMA tensor cores
    {
        dim3 grid(MTOK / 128, NPAD / 128);
        lm_head_hmma<<<grid, 256, LM_SMEM>>>(a2_ptr, b2_ptr, out);
    }
}

// round 7
// speedup vs baseline: 1.4074x; 1.1908x over previous
#include <cuda_runtime.h>
#include <cuda_fp16.h>
#include <math.h>
#include <stdint.h>

// Problem constants
#define VOCAB 50257
#define NPAD  50304              // 393 * 128
#define DMODEL 128
#define HID 256
#define BATCH 16
#define SEQ 128
#define GATES (3*HID)            // 768
#define MTOK (BATCH*SEQ)         // 2048
#define KB2 512                  // B-side concatenated K (2-term fp16 split)

// Scratch (__device__ globals per allocation-free rule)
__device__ float g_gx[MTOK * GATES];          // input-side gate projections
__device__ __half g_a2[MTOK * HID];           // fp16(h)   [2048,256]
__device__ __half g_b2[NPAD * KB2];           // [Bh | Bl] [50304,512]
__device__ float g_hbuf[2][BATCH * HID];      // double-buffered h exchange
__device__ int g_flags[4][32];                // per-group CTA arrival flags (128B apart)

__device__ __forceinline__ uint32_t smem_to_u32(const void* p) {
    uint32_t a;
    asm("{ .reg .u64 t; cvta.to.shared.u64 t, %1; cvt.u32.u64 %0, t; }"
        : "=r"(a) : "l"(p));
    return a;
}

// ---------------------------------------------------------------------------
// Stage 1: tiled TN SGEMM with gather + bias (proven)
// ---------------------------------------------------------------------------
template<bool HAS_IDX, bool HAS_BIAS>
__global__ __launch_bounds__(256)
void gemm_tn(const float* __restrict__ A, const int* __restrict__ idx,
             const float* __restrict__ Bm, const float* __restrict__ bias,
             float* __restrict__ C, int M, int N, int K)
{
    constexpr int BM = 128, BN = 128, BK = 16;
    __shared__ float As[BK][BM];
    __shared__ float Bs[BK][BN];

    const int tid = threadIdx.x;
    const int tx = tid & 15, ty = tid >> 4;
    const int m0 = blockIdx.y * BM, n0 = blockIdx.x * BN;

    int a_row[2], a_col[2], b_row[2], b_col[2];
    const float* a_src[2];
    const float* b_src[2];
    bool b_ok[2];
#pragma unroll
    for (int i = 0; i < 2; i++) {
        int f = tid * 2 + i;
        int r = f >> 2, cv = (f & 3) * 4;
        a_row[i] = r; a_col[i] = cv;
        b_row[i] = r; b_col[i] = cv;
        int gm = m0 + r;
        int src_row = HAS_IDX ? idx[gm] : gm;
        a_src[i] = A + (size_t)src_row * K + cv;
        int gn = n0 + r;
        b_ok[i]  = (gn < N);
        b_src[i] = Bm + (size_t)(b_ok[i] ? gn : 0) * K + cv;
    }

    float acc[8][8];
#pragma unroll
    for (int i = 0; i < 8; i++)
#pragma unroll
        for (int j = 0; j < 8; j++) acc[i][j] = 0.f;

    const int ntiles = K / BK;
    float4 a_reg[2], b_reg[2];
#pragma unroll
    for (int i = 0; i < 2; i++) {
        a_reg[i] = *(const float4*)(a_src[i]);
        b_reg[i] = b_ok[i] ? *(const float4*)(b_src[i]) : make_float4(0.f,0.f,0.f,0.f);
    }

    for (int kt = 0; kt < ntiles; kt++) {
#pragma unroll
        for (int i = 0; i < 2; i++) {
            As[a_col[i]+0][a_row[i]] = a_reg[i].x;
            As[a_col[i]+1][a_row[i]] = a_reg[i].y;
            As[a_col[i]+2][a_row[i]] = a_reg[i].z;
            As[a_col[i]+3][a_row[i]] = a_reg[i].w;
            Bs[b_col[i]+0][b_row[i]] = b_reg[i].x;
            Bs[b_col[i]+1][b_row[i]] = b_reg[i].y;
            Bs[b_col[i]+2][b_row[i]] = b_reg[i].z;
            Bs[b_col[i]+3][b_row[i]] = b_reg[i].w;
        }
        __syncthreads();

        if (kt + 1 < ntiles) {
            int koff = (kt + 1) * BK;
#pragma unroll
            for (int i = 0; i < 2; i++) {
                a_reg[i] = *(const float4*)(a_src[i] + koff);
                b_reg[i] = b_ok[i] ? *(const float4*)(b_src[i] + koff)
                                   : make_float4(0.f,0.f,0.f,0.f);
            }
        }

#pragma unroll
        for (int k = 0; k < BK; k++) {
            float4 a0 = *(const float4*)&As[k][ty * 8];
            float4 a1 = *(const float4*)&As[k][ty * 8 + 4];
            float4 b0 = *(const float4*)&Bs[k][tx * 8];
            float4 b1 = *(const float4*)&Bs[k][tx * 8 + 4];
            float av[8] = {a0.x,a0.y,a0.z,a0.w,a1.x,a1.y,a1.z,a1.w};
            float bv[8] = {b0.x,b0.y,b0.z,b0.w,b1.x,b1.y,b1.z,b1.w};
#pragma unroll
            for (int i = 0; i < 8; i++)
#pragma unroll
                for (int j = 0; j < 8; j++)
                    acc[i][j] += av[i] * bv[j];
        }
        __syncthreads();
    }

#pragma unroll
    for (int i = 0; i < 8; i++) {
        int gm = m0 + ty * 8 + i;
        float* crow = C + (size_t)gm * N + n0 + tx * 8;
#pragma unroll
        for (int j = 0; j < 8; j++) {
            int gn = n0 + tx * 8 + j;
            if (gn < N) {
                float v = acc[i][j];
                if (HAS_BIAS) v += bias[gn];
                crow[j] = v;
            }
        }
    }
}

// ---------------------------------------------------------------------------
// Stage 2: GRU scan v5. 4 groups x 8 CTAs. Group g owns batches [4g,4g+4).
// CTA j owns units [32j,32j+32): 96 W rows register-resident (k-split 4),
// batch-serial partial dots. 8-participant flag barrier per step.
// ---------------------------------------------------------------------------
#define GNC 8
#define GRU_T 384

__global__ __launch_bounds__(GRU_T)
void gru_scan5(const float* __restrict__ gx, const float* __restrict__ Whh,
               const float* __restrict__ bhh, __half* __restrict__ a2)
{
    __shared__ float H_sm[16 * 68];         // [(b*4+chunk)*68 + off]
    __shared__ float gh_sm[96][4];          // [row][batch]

    const int j   = blockIdx.x & 7;         // CTA in group
    const int grp = blockIdx.x >> 3;
    const int tid = threadIdx.x;
    const int rh  = tid >> 2;               // 0..95 local gate-row
    const int c   = tid & 3;                // k-chunk
    const int gate = rh >> 5;
    const int urow = rh & 31;
    const int grow = gate * HID + j * 32 + urow;

    // Register-resident W chunk (64 floats)
    float w[64];
    {
        const float4* src = (const float4*)(Whh + (size_t)grow * HID + c * 64);
#pragma unroll
        for (int i = 0; i < 16; i++) {
            float4 v = src[i];
            w[4*i] = v.x; w[4*i+1] = v.y; w[4*i+2] = v.z; w[4*i+3] = v.w;
        }
    }

    // h-update role (tid < 128): unit uu, local batch ub
    const int uu  = tid >> 2;
    const int ub  = tid & 3;
    const int uid = j * 32 + uu;
    const int bg  = grp * 4 + ub;
    float br = 0.f, bz = 0.f, bn = 0.f;
    if (tid < 128) { br = bhh[uid]; bz = bhh[HID + uid]; bn = bhh[2 * HID + uid]; }

    for (int i = tid; i < 16 * 68; i += GRU_T) H_sm[i] = 0.f;
    __syncthreads();

    for (int t = 0; t < SEQ; t++) {
        // prefetch gx operands (overlaps dot)
        float xr = 0.f, xz = 0.f, xn = 0.f;
        if (tid < 128) {
            const float* p = gx + (size_t)(bg * SEQ + t) * GATES;
            xr = p[uid]; xz = p[HID + uid]; xn = p[2 * HID + uid];
        }

        // batch-serial partial dots over this thread's k-chunk
        float sb[4];
#pragma unroll
        for (int b = 0; b < 4; b++) {
            const float* hB = &H_sm[(b * 4 + c) * 68];
            float s0 = 0.f, s1 = 0.f, s2 = 0.f, s3 = 0.f;
#pragma unroll
            for (int i = 0; i < 16; i++) {
                float4 h = *(const float4*)&hB[4 * i];
                s0 += w[4*i]   * h.x; s1 += w[4*i+1] * h.y;
                s2 += w[4*i+2] * h.z; s3 += w[4*i+3] * h.w;
            }
            sb[b] = (s0 + s1) + (s2 + s3);
        }
#pragma unroll
        for (int b = 0; b < 4; b++) {
            sb[b] += __shfl_down_sync(0xffffffffu, sb[b], 1, 4);
            sb[b] += __shfl_down_sync(0xffffffffu, sb[b], 2, 4);
        }
        if (c == 0)
            *(float4*)gh_sm[rh] = make_float4(sb[0], sb[1], sb[2], sb[3]);
        __syncthreads();

        if (tid < 128) {
            float hr = gh_sm[uu][ub]      + br;
            float hz = gh_sm[32 + uu][ub] + bz;
            float hn = gh_sm[64 + uu][ub] + bn;
            float hp = H_sm[(ub * 4 + (uid >> 6)) * 68 + (uid & 63)];
            float r = 1.f / (1.f + expf(-(xr + hr)));
            float z = 1.f / (1.f + expf(-(xz + hz)));
            float n = tanhf(xn + r * hn);
            float hnew = (1.f - z) * n + z * hp;
            g_hbuf[t & 1][bg * HID + uid] = hnew;
            a2[(size_t)(bg * SEQ + t) * HID + uid] = __float2half_rn(hnew);
        }
        __syncthreads();

        // 8-CTA group barrier: release store + 8-flag poll (1 sector)
        if (tid == 0)
            asm volatile("st.release.gpu.u32 [%0], %1;"
                         :: "l"(&g_flags[grp][j]), "r"(t + 1) : "memory");
        if (tid < GNC) {
            int v;
            do {
                asm volatile("ld.acquire.gpu.u32 %0, [%1];"
                             : "=r"(v) : "l"(&g_flags[grp][tid]) : "memory");
            } while (v < t + 1);
        }
        __syncthreads();

        // refresh group's H from exchange buffer (L2-coherent)
        if (tid < 256) {
            int b = tid >> 6, k4 = (tid & 63) * 4;
            const float4* src = (const float4*)&g_hbuf[t & 1][(grp * 4 + b) * HID + k4];
            float4 v;
            asm volatile("ld.global.cg.v4.f32 {%0,%1,%2,%3}, [%4];"
                         : "=f"(v.x), "=f"(v.y), "=f"(v.z), "=f"(v.w) : "l"(src));
            float* d = &H_sm[(b * 4 + (k4 >> 6)) * 68 + (k4 & 63)];
            d[0] = v.x; d[1] = v.y; d[2] = v.z; d[3] = v.w;
        }
        __syncthreads();
    }
}

// ---------------------------------------------------------------------------
// W_out -> B2 = [Bh fp16 | Bl fp16] (padded/zeroed to NPAD rows)
// ---------------------------------------------------------------------------
__global__ __launch_bounds__(256)
void conv_w2(const float* __restrict__ W, __half* __restrict__ B2)
{
    int idx = blockIdx.x * blockDim.x + threadIdx.x;
    int v = idx >> 6;
    int k4 = (idx & 63) * 4;
    if (v >= NPAD) return;

    __half2 h01, h23, l01, l23;
    if (v < VOCAB) {
        float4 x = *(const float4*)(W + (size_t)v * HID + k4);
        __half h0 = __float2half_rn(x.x);
        __half h1 = __float2half_rn(x.y);
        __half h2 = __float2half_rn(x.z);
        __half h3 = __float2half_rn(x.w);
        h01 = __halves2half2(h0, h1);
        h23 = __halves2half2(h2, h3);
        l01 = __halves2half2(__float2half_rn(x.x - __half2float(h0)),
                             __float2half_rn(x.y - __half2float(h1)));
        l23 = __halves2half2(__float2half_rn(x.z - __half2float(h2)),
                             __float2half_rn(x.w - __half2float(h3)));
    } else {
        h01 = h23 = l01 = l23 = __halves2half2(__float2half_rn(0.f),
                                               __float2half_rn(0.f));
    }
    __half2* row = (__half2*)(B2 + (size_t)v * KB2);
    row[(k4 >> 1)]             = h01;  row[(k4 >> 1) + 1]           = h23;
    row[(HID + k4) >> 1]       = l01;  row[((HID + k4) >> 1) + 1]   = l23;
}

// ---------------------------------------------------------------------------
// Stage 3: LM head via HMMA fp16, 2-term split. K=512 (B side); A (256 cols)
// read twice via kt&3. CTA 128x128, 8 warps (2x4), warp 64x32, cp.async.
// ---------------------------------------------------------------------------
#define LM_BK 64
#define LM_NT (KB2 / LM_BK)           // 8
#define LM_TILE_B 16384               // 128 rows * 128B
#define LM_STAGE_B (2 * LM_TILE_B)
#define LM_SMEM (2 * LM_STAGE_B)      // 65536

__device__ __forceinline__ void cp16(uint32_t saddr, const void* gaddr) {
    asm volatile("cp.async.cg.shared.global [%0], [%1], 16;"
                 :: "r"(saddr), "l"(gaddr));
}

__global__ __launch_bounds__(256, 2)
void lm_head_hmma(const __half* __restrict__ A2,
                  const __half* __restrict__ B2,
                  float* __restrict__ out)
{
    extern __shared__ char smem[];
    const uint32_t sbase = smem_to_u32(smem);

    const int tid = threadIdx.x;
    const int lane = tid & 31;
    const int wid = tid >> 5;
    const int m0 = blockIdx.x * 128;
    const int n0 = blockIdx.y * 128;
    const int wm = (wid >> 2) * 64;
    const int wn = (wid & 3) * 32;

    const int lg = lane >> 3, lr = lane & 7;
    const int row16 = ((lg & 1) << 3) + lr;
    const int csel  = lg >> 1;

    float acc[4][4][4];
#pragma unroll
    for (int i = 0; i < 4; i++)
#pragma unroll
        for (int j = 0; j < 4; j++)
#pragma unroll
            for (int k = 0; k < 4; k++) acc[i][j][k] = 0.f;

    auto issue = [&](int kt) {
        const uint32_t stage = sbase + (kt & 1) * LM_STAGE_B;
#pragma unroll
        for (int i = 0; i < 4; i++) {
            int q = i * 256 + tid;
            int row = q >> 3, c = q & 7;
            uint32_t soff = row * 128 + (((uint32_t)(c ^ (row & 7))) << 4);
            cp16(stage + soff,
                 A2 + (size_t)(m0 + row) * HID + (kt & 3) * LM_BK + c * 8);
            cp16(stage + LM_TILE_B + soff,
                 B2 + (size_t)(n0 + row) * KB2 + kt * LM_BK + c * 8);
        }
        asm volatile("cp.async.commit_group;" ::: "memory");
    };

    issue(0);

    for (int kt = 0; kt < LM_NT; kt++) {
        if (kt + 1 < LM_NT) {
            issue(kt + 1);
            asm volatile("cp.async.wait_group 1;" ::: "memory");
        } else {
            asm volatile("cp.async.wait_group 0;" ::: "memory");
        }
        __syncthreads();

        const uint32_t Ab = sbase + (kt & 1) * LM_STAGE_B;
        const uint32_t Bb = Ab + LM_TILE_B;

#pragma unroll
        for (int ks = 0; ks < 4; ks++) {
            const int kc = ks * 2;
            uint32_t a[4][4];
#pragma unroll
            for (int mt = 0; mt < 4; mt++) {
                int row = wm + mt * 16 + row16;
                uint32_t addr = Ab + row * 128 +
                    (((uint32_t)((kc + csel) ^ (row & 7))) << 4);
                asm volatile(
                    "ldmatrix.sync.aligned.m8n8.x4.shared.b16 {%0,%1,%2,%3}, [%4];"
                    : "=r"(a[mt][0]), "=r"(a[mt][1]), "=r"(a[mt][2]), "=r"(a[mt][3])
                    : "r"(addr));
            }
            uint32_t bf[4][2];
#pragma unroll
            for (int np = 0; np < 2; np++) {
                int row = wn + np * 16 + row16;
                uint32_t addr = Bb + row * 128 +
                    (((uint32_t)((kc + csel) ^ (row & 7))) << 4);
                uint32_t q0, q1, q2, q3;
                asm volatile(
                    "ldmatrix.sync.aligned.m8n8.x4.shared.b16 {%0,%1,%2,%3}, [%4];"
                    : "=r"(q0), "=r"(q1), "=r"(q2), "=r"(q3)
                    : "r"(addr));
                bf[np * 2][0] = q0;     bf[np * 2][1] = q2;
                bf[np * 2 + 1][0] = q1; bf[np * 2 + 1][1] = q3;
            }
#pragma unroll
            for (int mt = 0; mt < 4; mt++)
#pragma unroll
                for (int nt = 0; nt < 4; nt++) {
                    asm volatile(
                        "mma.sync.aligned.m16n8k16.row.col.f32.f16.f16.f32 "
                        "{%0,%1,%2,%3}, {%4,%5,%6,%7}, {%8,%9}, {%0,%1,%2,%3};"
                        : "+f"(acc[mt][nt][0]), "+f"(acc[mt][nt][1]),
                          "+f"(acc[mt][nt][2]), "+f"(acc[mt][nt][3])
                        : "r"(a[mt][0]), "r"(a[mt][1]), "r"(a[mt][2]), "r"(a[mt][3]),
                          "r"(bf[nt][0]), "r"(bf[nt][1]));
                }
        }
        __syncthreads();
    }

    const int elr = lane >> 2;
    const int elc = (lane & 3) * 2;
    const bool full = (n0 + 128 <= VOCAB);
#pragma unroll
    for (int mt = 0; mt < 4; mt++) {
#pragma unroll
        for (int nt = 0; nt < 4; nt++) {
            int gr = m0 + wm + mt * 16 + elr;
            int gc = n0 + wn + nt * 8 + elc;
            float* p0 = out + (size_t)gr * VOCAB + gc;
            float* p1 = out + (size_t)(gr + 8) * VOCAB + gc;
            if (full) {
                p0[0] = acc[mt][nt][0]; p0[1] = acc[mt][nt][1];
                p1[0] = acc[mt][nt][2]; p1[1] = acc[mt][nt][3];
            } else {
                if (gc < VOCAB)     { p0[0] = acc[mt][nt][0]; p1[0] = acc[mt][nt][2]; }
                if (gc + 1 < VOCAB) { p0[1] = acc[mt][nt][1]; p1[1] = acc[mt][nt][3]; }
            }
        }
    }
}

// ---------------------------------------------------------------------------
// Launch
// ---------------------------------------------------------------------------
extern "C" void kernel_launch(void* const* d_in, const int* in_sizes, int n_in,
                              void* d_out, int out_size)
{
    const int*   ids   = (const int*)  d_in[0];
    const float* embed = (const float*)d_in[1];
    const float* W_ih  = (const float*)d_in[2];
    const float* b_ih  = (const float*)d_in[3];
    const float* W_hh  = (const float*)d_in[4];
    const float* b_hh  = (const float*)d_in[5];
    const float* W_out = (const float*)d_in[6];
    float* out = (float*)d_out;

    float* gx_ptr;
    __half *a2_ptr, *b2_ptr;
    void* flags_ptr;
    cudaGetSymbolAddress((void**)&gx_ptr, g_gx);
    cudaGetSymbolAddress((void**)&a2_ptr, g_a2);
    cudaGetSymbolAddress((void**)&b2_ptr, g_b2);
    cudaGetSymbolAddress(&flags_ptr, g_flags);

    cudaFuncSetAttribute(lm_head_hmma,
                         cudaFuncAttributeMaxDynamicSharedMemorySize, LM_SMEM);

    // reset barrier flags (graph-capturable memset node)
    cudaMemsetAsync(flags_ptr, 0, sizeof(int) * 4 * 32);

    // 0) B2 = [Bh | Bl] fp16 split of W_out
    {
        int nthreads = NPAD * 64;
        conv_w2<<<(nthreads + 255) / 256, 256>>>(W_out, b2_ptr);
    }

    // 1) gx = embed[ids] @ W_ih^T + b_ih
    {
        dim3 grid(GATES / 128, MTOK / 128);
        gemm_tn<true, true><<<grid, 256>>>(embed, ids, W_ih, b_ih,
                                           gx_ptr, MTOK, GATES, DMODEL);
    }

    // 2) GRU scan v5 (4 groups x 8 CTAs)
    gru_scan5<<<32, GRU_T>>>(gx_ptr, W_hh, b_hh, a2_ptr);

    // 3) LM head on HMMA fp16
    {
        dim3 grid(MTOK / 128, NPAD / 128);
        lm_head_hmma<<<grid, 256, LM_SMEM>>>(a2_ptr, b2_ptr, out);
    }
}

// round 8
// speedup vs baseline: 1.6789x; 1.1930x over previous
#include <cuda_runtime.h>
#include <cuda_fp16.h>
#include <math.h>
#include <stdint.h>

// Problem constants
#define VOCAB 50257
#define NPAD  50304              // 393 * 128
#define DMODEL 128
#define HID 256
#define BATCH 16
#define SEQ 128
#define GATES (3*HID)            // 768
#define MTOK (BATCH*SEQ)         // 2048
#define KB2 512                  // B-side concatenated K (2-term fp16 split)

// Scratch (__device__ globals per allocation-free rule)
__device__ float g_gx[MTOK * GATES];          // input-side gate projections
__device__ __half g_a2[MTOK * HID];           // fp16(h)   [2048,256]
__device__ __half g_b2[NPAD * KB2];           // [Bh | Bl] [50304,512]
__device__ float g_hbuf[2][BATCH * HID];      // double-buffered h exchange
__device__ int g_flags[16][32];               // per-group CTA arrival flags (128B apart)

__device__ __forceinline__ uint32_t smem_to_u32(const void* p) {
    uint32_t a;
    asm("{ .reg .u64 t; cvta.to.shared.u64 t, %1; cvt.u32.u64 %0, t; }"
        : "=r"(a) : "l"(p));
    return a;
}

// ---------------------------------------------------------------------------
// Stage 1: tiled TN SGEMM with gather + bias (proven)
// ---------------------------------------------------------------------------
template<bool HAS_IDX, bool HAS_BIAS>
__global__ __launch_bounds__(256)
void gemm_tn(const float* __restrict__ A, const int* __restrict__ idx,
             const float* __restrict__ Bm, const float* __restrict__ bias,
             float* __restrict__ C, int M, int N, int K)
{
    constexpr int BM = 128, BN = 128, BK = 16;
    __shared__ float As[BK][BM];
    __shared__ float Bs[BK][BN];

    const int tid = threadIdx.x;
    const int tx = tid & 15, ty = tid >> 4;
    const int m0 = blockIdx.y * BM, n0 = blockIdx.x * BN;

    int a_row[2], a_col[2], b_row[2], b_col[2];
    const float* a_src[2];
    const float* b_src[2];
    bool b_ok[2];
#pragma unroll
    for (int i = 0; i < 2; i++) {
        int f = tid * 2 + i;
        int r = f >> 2, cv = (f & 3) * 4;
        a_row[i] = r; a_col[i] = cv;
        b_row[i] = r; b_col[i] = cv;
        int gm = m0 + r;
        int src_row = HAS_IDX ? idx[gm] : gm;
        a_src[i] = A + (size_t)src_row * K + cv;
        int gn = n0 + r;
        b_ok[i]  = (gn < N);
        b_src[i] = Bm + (size_t)(b_ok[i] ? gn : 0) * K + cv;
    }

    float acc[8][8];
#pragma unroll
    for (int i = 0; i < 8; i++)
#pragma unroll
        for (int j = 0; j < 8; j++) acc[i][j] = 0.f;

    const int ntiles = K / BK;
    float4 a_reg[2], b_reg[2];
#pragma unroll
    for (int i = 0; i < 2; i++) {
        a_reg[i] = *(const float4*)(a_src[i]);
        b_reg[i] = b_ok[i] ? *(const float4*)(b_src[i]) : make_float4(0.f,0.f,0.f,0.f);
    }

    for (int kt = 0; kt < ntiles; kt++) {
#pragma unroll
        for (int i = 0; i < 2; i++) {
            As[a_col[i]+0][a_row[i]] = a_reg[i].x;
            As[a_col[i]+1][a_row[i]] = a_reg[i].y;
            As[a_col[i]+2][a_row[i]] = a_reg[i].z;
            As[a_col[i]+3][a_row[i]] = a_reg[i].w;
            Bs[b_col[i]+0][b_row[i]] = b_reg[i].x;
            Bs[b_col[i]+1][b_row[i]] = b_reg[i].y;
            Bs[b_col[i]+2][b_row[i]] = b_reg[i].z;
            Bs[b_col[i]+3][b_row[i]] = b_reg[i].w;
        }
        __syncthreads();

        if (kt + 1 < ntiles) {
            int koff = (kt + 1) * BK;
#pragma unroll
            for (int i = 0; i < 2; i++) {
                a_reg[i] = *(const float4*)(a_src[i] + koff);
                b_reg[i] = b_ok[i] ? *(const float4*)(b_src[i] + koff)
                                   : make_float4(0.f,0.f,0.f,0.f);
            }
        }

#pragma unroll
        for (int k = 0; k < BK; k++) {
            float4 a0 = *(const float4*)&As[k][ty * 8];
            float4 a1 = *(const float4*)&As[k][ty * 8 + 4];
            float4 b0 = *(const float4*)&Bs[k][tx * 8];
            float4 b1 = *(const float4*)&Bs[k][tx * 8 + 4];
            float av[8] = {a0.x,a0.y,a0.z,a0.w,a1.x,a1.y,a1.z,a1.w};
            float bv[8] = {b0.x,b0.y,b0.z,b0.w,b1.x,b1.y,b1.z,b1.w};
#pragma unroll
            for (int i = 0; i < 8; i++)
#pragma unroll
                for (int j = 0; j < 8; j++)
                    acc[i][j] += av[i] * bv[j];
        }
        __syncthreads();
    }

#pragma unroll
    for (int i = 0; i < 8; i++) {
        int gm = m0 + ty * 8 + i;
        float* crow = C + (size_t)gm * N + n0 + tx * 8;
#pragma unroll
        for (int j = 0; j < 8; j++) {
            int gn = n0 + tx * 8 + j;
            if (gn < N) {
                float v = acc[i][j];
                if (HAS_BIAS) v += bias[gn];
                crow[j] = v;
            }
        }
    }
}

// ---------------------------------------------------------------------------
// Stage 2: GRU scan v6. 16 groups (one batch each) x 8 CTAs = 128 CTAs.
// CTA j owns units [32j,32j+32): 96 W rows register-resident (k-split 4),
// single-batch dot. 8-participant flag barrier per step.
// ---------------------------------------------------------------------------
#define GNC 8
#define GRU_T 384

__global__ __launch_bounds__(GRU_T)
void gru_scan6(const float* __restrict__ gx, const float* __restrict__ Whh,
               const float* __restrict__ bhh, __half* __restrict__ a2)
{
    __shared__ float H_sm[4 * 68];          // 4 chunks of 64 units, stride 68
    __shared__ float gh_sm[96];

    const int j   = blockIdx.x & 7;         // CTA in group
    const int bg  = blockIdx.x >> 3;        // batch (group) 0..15
    const int tid = threadIdx.x;
    const int rh  = tid >> 2;               // 0..95 local gate-row
    const int c   = tid & 3;                // k-chunk
    const int gate = rh >> 5;
    const int urow = rh & 31;
    const int grow = gate * HID + j * 32 + urow;

    // Register-resident W chunk (64 floats)
    float w[64];
    {
        const float4* src = (const float4*)(Whh + (size_t)grow * HID + c * 64);
#pragma unroll
        for (int i = 0; i < 16; i++) {
            float4 v = src[i];
            w[4*i] = v.x; w[4*i+1] = v.y; w[4*i+2] = v.z; w[4*i+3] = v.w;
        }
    }

    // h-update role (tid < 32): one unit per thread
    const int uid = j * 32 + tid;
    float br = 0.f, bz = 0.f, bn = 0.f;
    if (tid < 32) { br = bhh[uid]; bz = bhh[HID + uid]; bn = bhh[2 * HID + uid]; }

    for (int i = tid; i < 4 * 68; i += GRU_T) H_sm[i] = 0.f;
    __syncthreads();

    for (int t = 0; t < SEQ; t++) {
        // prefetch gx operands (overlaps dot)
        float xr = 0.f, xz = 0.f, xn = 0.f;
        if (tid < 32) {
            const float* p = gx + (size_t)(bg * SEQ + t) * GATES;
            xr = p[uid]; xz = p[HID + uid]; xn = p[2 * HID + uid];
        }

        // partial dot over this thread's k-chunk (single batch)
        const float* hB = &H_sm[c * 68];
        float s0 = 0.f, s1 = 0.f, s2 = 0.f, s3 = 0.f;
#pragma unroll
        for (int i = 0; i < 16; i++) {
            float4 h = *(const float4*)&hB[4 * i];
            s0 += w[4*i]   * h.x; s1 += w[4*i+1] * h.y;
            s2 += w[4*i+2] * h.z; s3 += w[4*i+3] * h.w;
        }
        float s = (s0 + s1) + (s2 + s3);
        s += __shfl_down_sync(0xffffffffu, s, 1, 4);
        s += __shfl_down_sync(0xffffffffu, s, 2, 4);
        if (c == 0) gh_sm[rh] = s;
        __syncthreads();

        if (tid < 32) {
            float hr = gh_sm[tid]      + br;
            float hz = gh_sm[32 + tid] + bz;
            float hn = gh_sm[64 + tid] + bn;
            float hp = H_sm[(uid >> 6) * 68 + (uid & 63)];
            float r = __fdividef(1.f, 1.f + __expf(-(xr + hr)));
            float z = __fdividef(1.f, 1.f + __expf(-(xz + hz)));
            float targ = xn + r * hn;
            targ = fminf(15.f, fmaxf(-15.f, targ));
            float e2 = __expf(2.f * targ);
            float n = 1.f - __fdividef(2.f, e2 + 1.f);
            float hnew = (1.f - z) * n + z * hp;
            g_hbuf[t & 1][bg * HID + uid] = hnew;
            a2[(size_t)(bg * SEQ + t) * HID + uid] = __float2half_rn(hnew);
        }
        __syncthreads();

        // 8-CTA group barrier: release store + 8-flag poll (one sector)
        if (tid == 0)
            asm volatile("st.release.gpu.u32 [%0], %1;"
                         :: "l"(&g_flags[bg][j]), "r"(t + 1) : "memory");
        if (tid < GNC) {
            int v;
            do {
                asm volatile("ld.acquire.gpu.u32 %0, [%1];"
                             : "=r"(v) : "l"(&g_flags[bg][tid]) : "memory");
            } while (v < t + 1);
        }
        __syncthreads();

        // refresh this batch's H (1 KB, L2-coherent)
        if (tid < 64) {
            int k4 = tid * 4;
            const float4* src = (const float4*)&g_hbuf[t & 1][bg * HID + k4];
            float4 v;
            asm volatile("ld.global.cg.v4.f32 {%0,%1,%2,%3}, [%4];"
                         : "=f"(v.x), "=f"(v.y), "=f"(v.z), "=f"(v.w) : "l"(src));
            float* d = &H_sm[(k4 >> 6) * 68 + (k4 & 63)];
            d[0] = v.x; d[1] = v.y; d[2] = v.z; d[3] = v.w;
        }
        __syncthreads();
    }
}

// ---------------------------------------------------------------------------
// W_out -> B2 = [Bh fp16 | Bl fp16] (padded/zeroed to NPAD rows)
// ---------------------------------------------------------------------------
__global__ __launch_bounds__(256)
void conv_w2(const float* __restrict__ W, __half* __restrict__ B2)
{
    int idx = blockIdx.x * blockDim.x + threadIdx.x;
    int v = idx >> 6;
    int k4 = (idx & 63) * 4;
    if (v >= NPAD) return;

    __half2 h01, h23, l01, l23;
    if (v < VOCAB) {
        float4 x = *(const float4*)(W + (size_t)v * HID + k4);
        __half h0 = __float2half_rn(x.x);
        __half h1 = __float2half_rn(x.y);
        __half h2 = __float2half_rn(x.z);
        __half h3 = __float2half_rn(x.w);
        h01 = __halves2half2(h0, h1);
        h23 = __halves2half2(h2, h3);
        l01 = __halves2half2(__float2half_rn(x.x - __half2float(h0)),
                             __float2half_rn(x.y - __half2float(h1)));
        l23 = __halves2half2(__float2half_rn(x.z - __half2float(h2)),
                             __float2half_rn(x.w - __half2float(h3)));
    } else {
        h01 = h23 = l01 = l23 = __halves2half2(__float2half_rn(0.f),
                                               __float2half_rn(0.f));
    }
    __half2* row = (__half2*)(B2 + (size_t)v * KB2);
    row[(k4 >> 1)]             = h01;  row[(k4 >> 1) + 1]           = h23;
    row[(HID + k4) >> 1]       = l01;  row[((HID + k4) >> 1) + 1]   = l23;
}

// ---------------------------------------------------------------------------
// Stage 3: LM head via HMMA fp16, 2-term split. K=512 (B side); A (256 cols)
// read twice via kt&3. CTA 128x128, 8 warps (2x4), warp 64x32, cp.async.
// ---------------------------------------------------------------------------
#define LM_BK 64
#define LM_NT (KB2 / LM_BK)           // 8
#define LM_TILE_B 16384               // 128 rows * 128B
#define LM_STAGE_B (2 * LM_TILE_B)
#define LM_SMEM (2 * LM_STAGE_B)      // 65536

__device__ __forceinline__ void cp16(uint32_t saddr, const void* gaddr) {
    asm volatile("cp.async.cg.shared.global [%0], [%1], 16;"
                 :: "r"(saddr), "l"(gaddr));
}

__global__ __launch_bounds__(256, 2)
void lm_head_hmma(const __half* __restrict__ A2,
                  const __half* __restrict__ B2,
                  float* __restrict__ out)
{
    extern __shared__ char smem[];
    const uint32_t sbase = smem_to_u32(smem);

    const int tid = threadIdx.x;
    const int lane = tid & 31;
    const int wid = tid >> 5;
    const int m0 = blockIdx.x * 128;
    const int n0 = blockIdx.y * 128;
    const int wm = (wid >> 2) * 64;
    const int wn = (wid & 3) * 32;

    const int lg = lane >> 3, lr = lane & 7;
    const int row16 = ((lg & 1) << 3) + lr;
    const int csel  = lg >> 1;

    float acc[4][4][4];
#pragma unroll
    for (int i = 0; i < 4; i++)
#pragma unroll
        for (int j = 0; j < 4; j++)
#pragma unroll
            for (int k = 0; k < 4; k++) acc[i][j][k] = 0.f;

    auto issue = [&](int kt) {
        const uint32_t stage = sbase + (kt & 1) * LM_STAGE_B;
#pragma unroll
        for (int i = 0; i < 4; i++) {
            int q = i * 256 + tid;
            int row = q >> 3, c = q & 7;
            uint32_t soff = row * 128 + (((uint32_t)(c ^ (row & 7))) << 4);
            cp16(stage + soff,
                 A2 + (size_t)(m0 + row) * HID + (kt & 3) * LM_BK + c * 8);
            cp16(stage + LM_TILE_B + soff,
                 B2 + (size_t)(n0 + row) * KB2 + kt * LM_BK + c * 8);
        }
        asm volatile("cp.async.commit_group;" ::: "memory");
    };

    issue(0);

    for (int kt = 0; kt < LM_NT; kt++) {
        if (kt + 1 < LM_NT) {
            issue(kt + 1);
            asm volatile("cp.async.wait_group 1;" ::: "memory");
        } else {
            asm volatile("cp.async.wait_group 0;" ::: "memory");
        }
        __syncthreads();

        const uint32_t Ab = sbase + (kt & 1) * LM_STAGE_B;
        const uint32_t Bb = Ab + LM_TILE_B;

#pragma unroll
        for (int ks = 0; ks < 4; ks++) {
            const int kc = ks * 2;
            uint32_t a[4][4];
#pragma unroll
            for (int mt = 0; mt < 4; mt++) {
                int row = wm + mt * 16 + row16;
                uint32_t addr = Ab + row * 128 +
                    (((uint32_t)((kc + csel) ^ (row & 7))) << 4);
                asm volatile(
                    "ldmatrix.sync.aligned.m8n8.x4.shared.b16 {%0,%1,%2,%3}, [%4];"
                    : "=r"(a[mt][0]), "=r"(a[mt][1]), "=r"(a[mt][2]), "=r"(a[mt][3])
                    : "r"(addr));
            }
            uint32_t bf[4][2];
#pragma unroll
            for (int np = 0; np < 2; np++) {
                int row = wn + np * 16 + row16;
                uint32_t addr = Bb + row * 128 +
                    (((uint32_t)((kc + csel) ^ (row & 7))) << 4);
                uint32_t q0, q1, q2, q3;
                asm volatile(
                    "ldmatrix.sync.aligned.m8n8.x4.shared.b16 {%0,%1,%2,%3}, [%4];"
                    : "=r"(q0), "=r"(q1), "=r"(q2), "=r"(q3)
                    : "r"(addr));
                bf[np * 2][0] = q0;     bf[np * 2][1] = q2;
                bf[np * 2 + 1][0] = q1; bf[np * 2 + 1][1] = q3;
            }
#pragma unroll
            for (int mt = 0; mt < 4; mt++)
#pragma unroll
                for (int nt = 0; nt < 4; nt++) {
                    asm volatile(
                        "mma.sync.aligned.m16n8k16.row.col.f32.f16.f16.f32 "
                        "{%0,%1,%2,%3}, {%4,%5,%6,%7}, {%8,%9}, {%0,%1,%2,%3};"
                        : "+f"(acc[mt][nt][0]), "+f"(acc[mt][nt][1]),
                          "+f"(acc[mt][nt][2]), "+f"(acc[mt][nt][3])
                        : "r"(a[mt][0]), "r"(a[mt][1]), "r"(a[mt][2]), "r"(a[mt][3]),
                          "r"(bf[nt][0]), "r"(bf[nt][1]));
                }
        }
        __syncthreads();
    }

    const int elr = lane >> 2;
    const int elc = (lane & 3) * 2;
    const bool full = (n0 + 128 <= VOCAB);
#pragma unroll
    for (int mt = 0; mt < 4; mt++) {
#pragma unroll
        for (int nt = 0; nt < 4; nt++) {
            int gr = m0 + wm + mt * 16 + elr;
            int gc = n0 + wn + nt * 8 + elc;
            float* p0 = out + (size_t)gr * VOCAB + gc;
            float* p1 = out + (size_t)(gr + 8) * VOCAB + gc;
            if (full) {
                p0[0] = acc[mt][nt][0]; p0[1] = acc[mt][nt][1];
                p1[0] = acc[mt][nt][2]; p1[1] = acc[mt][nt][3];
            } else {
                if (gc < VOCAB)     { p0[0] = acc[mt][nt][0]; p1[0] = acc[mt][nt][2]; }
                if (gc + 1 < VOCAB) { p0[1] = acc[mt][nt][1]; p1[1] = acc[mt][nt][3]; }
            }
        }
    }
}

// ---------------------------------------------------------------------------
// Launch
// ---------------------------------------------------------------------------
extern "C" void kernel_launch(void* const* d_in, const int* in_sizes, int n_in,
                              void* d_out, int out_size)
{
    const int*   ids   = (const int*)  d_in[0];
    const float* embed = (const float*)d_in[1];
    const float* W_ih  = (const float*)d_in[2];
    const float* b_ih  = (const float*)d_in[3];
    const float* W_hh  = (const float*)d_in[4];
    const float* b_hh  = (const float*)d_in[5];
    const float* W_out = (const float*)d_in[6];
    float* out = (float*)d_out;

    float* gx_ptr;
    __half *a2_ptr, *b2_ptr;
    void* flags_ptr;
    cudaGetSymbolAddress((void**)&gx_ptr, g_gx);
    cudaGetSymbolAddress((void**)&a2_ptr, g_a2);
    cudaGetSymbolAddress((void**)&b2_ptr, g_b2);
    cudaGetSymbolAddress(&flags_ptr, g_flags);

    cudaFuncSetAttribute(lm_head_hmma,
                         cudaFuncAttributeMaxDynamicSharedMemorySize, LM_SMEM);

    // reset barrier flags (graph-capturable memset node)
    cudaMemsetAsync(flags_ptr, 0, sizeof(int) * 16 * 32);

    // 0) B2 = [Bh | Bl] fp16 split of W_out
    {
        int nthreads = NPAD * 64;
        conv_w2<<<(nthreads + 255) / 256, 256>>>(W_out, b2_ptr);
    }

    // 1) gx = embed[ids] @ W_ih^T + b_ih
    {
        dim3 grid(GATES / 128, MTOK / 128);
        gemm_tn<true, true><<<grid, 256>>>(embed, ids, W_ih, b_ih,
                                           gx_ptr, MTOK, GATES, DMODEL);
    }

    // 2) GRU scan v6 (16 groups x 8 CTAs)
    gru_scan6<<<128, GRU_T>>>(gx_ptr, W_hh, b_hh, a2_ptr);

    // 3) LM head on HMMA fp16
    {
        dim3 grid(MTOK / 128, NPAD / 128);
        lm_head_hmma<<<grid, 256, LM_SMEM>>>(a2_ptr, b2_ptr, out);
    }
}

// round 9
// speedup vs baseline: 2.1208x; 1.2632x over previous
#include <cuda_runtime.h>
#include <cuda_fp16.h>
#include <math.h>
#include <stdint.h>

// Problem constants
#define VOCAB 50257
#define NPAD  50304              // 393 * 128
#define DMODEL 128
#define HID 256
#define BATCH 16
#define SEQ 128
#define GATES (3*HID)            // 768
#define MTOK (BATCH*SEQ)         // 2048

// Scratch (__device__ globals per allocation-free rule)
__device__ float g_gx[MTOK * GATES];          // input-side gate projections
__device__ __half g_a2[MTOK * HID];           // fp16(h)    [2048,256]
__device__ __half g_b2[NPAD * HID];           // fp16(W_out)[50304,256]
__device__ float g_hbuf[2][BATCH * HID];      // double-buffered h exchange
__device__ int g_flags[16][32];               // per-group CTA arrival flags (128B apart)

__device__ __forceinline__ uint32_t smem_to_u32(const void* p) {
    uint32_t a;
    asm("{ .reg .u64 t; cvta.to.shared.u64 t, %1; cvt.u32.u64 %0, t; }"
        : "=r"(a) : "l"(p));
    return a;
}

// ---------------------------------------------------------------------------
// Stage 1: tiled TN SGEMM with gather + bias (proven)
// ---------------------------------------------------------------------------
template<bool HAS_IDX, bool HAS_BIAS>
__global__ __launch_bounds__(256)
void gemm_tn(const float* __restrict__ A, const int* __restrict__ idx,
             const float* __restrict__ Bm, const float* __restrict__ bias,
             float* __restrict__ C, int M, int N, int K)
{
    constexpr int BM = 128, BN = 128, BK = 16;
    __shared__ float As[BK][BM];
    __shared__ float Bs[BK][BN];

    const int tid = threadIdx.x;
    const int tx = tid & 15, ty = tid >> 4;
    const int m0 = blockIdx.y * BM, n0 = blockIdx.x * BN;

    int a_row[2], a_col[2], b_row[2], b_col[2];
    const float* a_src[2];
    const float* b_src[2];
    bool b_ok[2];
#pragma unroll
    for (int i = 0; i < 2; i++) {
        int f = tid * 2 + i;
        int r = f >> 2, cv = (f & 3) * 4;
        a_row[i] = r; a_col[i] = cv;
        b_row[i] = r; b_col[i] = cv;
        int gm = m0 + r;
        int src_row = HAS_IDX ? idx[gm] : gm;
        a_src[i] = A + (size_t)src_row * K + cv;
        int gn = n0 + r;
        b_ok[i]  = (gn < N);
        b_src[i] = Bm + (size_t)(b_ok[i] ? gn : 0) * K + cv;
    }

    float acc[8][8];
#pragma unroll
    for (int i = 0; i < 8; i++)
#pragma unroll
        for (int j = 0; j < 8; j++) acc[i][j] = 0.f;

    const int ntiles = K / BK;
    float4 a_reg[2], b_reg[2];
#pragma unroll
    for (int i = 0; i < 2; i++) {
        a_reg[i] = *(const float4*)(a_src[i]);
        b_reg[i] = b_ok[i] ? *(const float4*)(b_src[i]) : make_float4(0.f,0.f,0.f,0.f);
    }

    for (int kt = 0; kt < ntiles; kt++) {
#pragma unroll
        for (int i = 0; i < 2; i++) {
            As[a_col[i]+0][a_row[i]] = a_reg[i].x;
            As[a_col[i]+1][a_row[i]] = a_reg[i].y;
            As[a_col[i]+2][a_row[i]] = a_reg[i].z;
            As[a_col[i]+3][a_row[i]] = a_reg[i].w;
            Bs[b_col[i]+0][b_row[i]] = b_reg[i].x;
            Bs[b_col[i]+1][b_row[i]] = b_reg[i].y;
            Bs[b_col[i]+2][b_row[i]] = b_reg[i].z;
            Bs[b_col[i]+3][b_row[i]] = b_reg[i].w;
        }
        __syncthreads();

        if (kt + 1 < ntiles) {
            int koff = (kt + 1) * BK;
#pragma unroll
            for (int i = 0; i < 2; i++) {
                a_reg[i] = *(const float4*)(a_src[i] + koff);
                b_reg[i] = b_ok[i] ? *(const float4*)(b_src[i] + koff)
                                   : make_float4(0.f,0.f,0.f,0.f);
            }
        }

#pragma unroll
        for (int k = 0; k < BK; k++) {
            float4 a0 = *(const float4*)&As[k][ty * 8];
            float4 a1 = *(const float4*)&As[k][ty * 8 + 4];
            float4 b0 = *(const float4*)&Bs[k][tx * 8];
            float4 b1 = *(const float4*)&Bs[k][tx * 8 + 4];
            float av[8] = {a0.x,a0.y,a0.z,a0.w,a1.x,a1.y,a1.z,a1.w};
            float bv[8] = {b0.x,b0.y,b0.z,b0.w,b1.x,b1.y,b1.z,b1.w};
#pragma unroll
            for (int i = 0; i < 8; i++)
#pragma unroll
                for (int j = 0; j < 8; j++)
                    acc[i][j] += av[i] * bv[j];
        }
        __syncthreads();
    }

#pragma unroll
    for (int i = 0; i < 8; i++) {
        int gm = m0 + ty * 8 + i;
        float* crow = C + (size_t)gm * N + n0 + tx * 8;
#pragma unroll
        for (int j = 0; j < 8; j++) {
            int gn = n0 + tx * 8 + j;
            if (gn < N) {
                float v = acc[i][j];
                if (HAS_BIAS) v += bias[gn];
                crow[j] = v;
            }
        }
    }
}

// ---------------------------------------------------------------------------
// Stage 2: GRU scan v6 (proven). 16 groups (one batch each) x 8 CTAs.
// ---------------------------------------------------------------------------
#define GNC 8
#define GRU_T 384

__global__ __launch_bounds__(GRU_T)
void gru_scan6(const float* __restrict__ gx, const float* __restrict__ Whh,
               const float* __restrict__ bhh, __half* __restrict__ a2)
{
    __shared__ float H_sm[4 * 68];          // 4 chunks of 64 units, stride 68
    __shared__ float gh_sm[96];

    const int j   = blockIdx.x & 7;         // CTA in group
    const int bg  = blockIdx.x >> 3;        // batch (group) 0..15
    const int tid = threadIdx.x;
    const int rh  = tid >> 2;               // 0..95 local gate-row
    const int c   = tid & 3;                // k-chunk
    const int gate = rh >> 5;
    const int urow = rh & 31;
    const int grow = gate * HID + j * 32 + urow;

    // Register-resident W chunk (64 floats)
    float w[64];
    {
        const float4* src = (const float4*)(Whh + (size_t)grow * HID + c * 64);
#pragma unroll
        for (int i = 0; i < 16; i++) {
            float4 v = src[i];
            w[4*i] = v.x; w[4*i+1] = v.y; w[4*i+2] = v.z; w[4*i+3] = v.w;
        }
    }

    const int uid = j * 32 + tid;
    float br = 0.f, bz = 0.f, bn = 0.f;
    if (tid < 32) { br = bhh[uid]; bz = bhh[HID + uid]; bn = bhh[2 * HID + uid]; }

    for (int i = tid; i < 4 * 68; i += GRU_T) H_sm[i] = 0.f;
    __syncthreads();

    for (int t = 0; t < SEQ; t++) {
        float xr = 0.f, xz = 0.f, xn = 0.f;
        if (tid < 32) {
            const float* p = gx + (size_t)(bg * SEQ + t) * GATES;
            xr = p[uid]; xz = p[HID + uid]; xn = p[2 * HID + uid];
        }

        const float* hB = &H_sm[c * 68];
        float s0 = 0.f, s1 = 0.f, s2 = 0.f, s3 = 0.f;
#pragma unroll
        for (int i = 0; i < 16; i++) {
            float4 h = *(const float4*)&hB[4 * i];
            s0 += w[4*i]   * h.x; s1 += w[4*i+1] * h.y;
            s2 += w[4*i+2] * h.z; s3 += w[4*i+3] * h.w;
        }
        float s = (s0 + s1) + (s2 + s3);
        s += __shfl_down_sync(0xffffffffu, s, 1, 4);
        s += __shfl_down_sync(0xffffffffu, s, 2, 4);
        if (c == 0) gh_sm[rh] = s;
        __syncthreads();

        if (tid < 32) {
            float hr = gh_sm[tid]      + br;
            float hz = gh_sm[32 + tid] + bz;
            float hn = gh_sm[64 + tid] + bn;
            float hp = H_sm[(uid >> 6) * 68 + (uid & 63)];
            float r = __fdividef(1.f, 1.f + __expf(-(xr + hr)));
            float z = __fdividef(1.f, 1.f + __expf(-(xz + hz)));
            float targ = xn + r * hn;
            targ = fminf(15.f, fmaxf(-15.f, targ));
            float e2 = __expf(2.f * targ);
            float n = 1.f - __fdividef(2.f, e2 + 1.f);
            float hnew = (1.f - z) * n + z * hp;
            g_hbuf[t & 1][bg * HID + uid] = hnew;
            a2[(size_t)(bg * SEQ + t) * HID + uid] = __float2half_rn(hnew);
        }
        __syncthreads();

        if (tid == 0)
            asm volatile("st.release.gpu.u32 [%0], %1;"
                         :: "l"(&g_flags[bg][j]), "r"(t + 1) : "memory");
        if (tid < GNC) {
            int v;
            do {
                asm volatile("ld.acquire.gpu.u32 %0, [%1];"
                             : "=r"(v) : "l"(&g_flags[bg][tid]) : "memory");
            } while (v < t + 1);
        }
        __syncthreads();

        if (tid < 64) {
            int k4 = tid * 4;
            const float4* src = (const float4*)&g_hbuf[t & 1][bg * HID + k4];
            float4 v;
            asm volatile("ld.global.cg.v4.f32 {%0,%1,%2,%3}, [%4];"
                         : "=f"(v.x), "=f"(v.y), "=f"(v.z), "=f"(v.w) : "l"(src));
            float* d = &H_sm[(k4 >> 6) * 68 + (k4 & 63)];
            d[0] = v.x; d[1] = v.y; d[2] = v.z; d[3] = v.w;
        }
        __syncthreads();
    }
}

// ---------------------------------------------------------------------------
// W_out -> fp16 (padded/zeroed to NPAD rows)
// ---------------------------------------------------------------------------
__global__ __launch_bounds__(256)
void conv_w1(const float* __restrict__ W, __half* __restrict__ B2)
{
    int idx = blockIdx.x * blockDim.x + threadIdx.x;   // one per 4 k-elems
    int v = idx >> 6;
    int k4 = (idx & 63) * 4;
    if (v >= NPAD) return;

    __half2 h01, h23;
    if (v < VOCAB) {
        float4 x = *(const float4*)(W + (size_t)v * HID + k4);
        h01 = __halves2half2(__float2half_rn(x.x), __float2half_rn(x.y));
        h23 = __halves2half2(__float2half_rn(x.z), __float2half_rn(x.w));
    } else {
        h01 = h23 = __halves2half2(__float2half_rn(0.f), __float2half_rn(0.f));
    }
    __half2* row = (__half2*)(B2 + (size_t)v * HID);
    row[(k4 >> 1)]     = h01;
    row[(k4 >> 1) + 1] = h23;
}

// ---------------------------------------------------------------------------
// Stage 3: LM head via HMMA fp16, single-term, K=256.
// CTA 128x128, 8 warps (2x4), warp 64x32, BK=64, cp.async 2-stage.
// ---------------------------------------------------------------------------
#define LM_BK 64
#define LM_NT (HID / LM_BK)           // 4
#define LM_TILE_B 16384               // 128 rows * 128B
#define LM_STAGE_B (2 * LM_TILE_B)
#define LM_SMEM (2 * LM_STAGE_B)      // 65536

__device__ __forceinline__ void cp16(uint32_t saddr, const void* gaddr) {
    asm volatile("cp.async.cg.shared.global [%0], [%1], 16;"
                 :: "r"(saddr), "l"(gaddr));
}

__global__ __launch_bounds__(256, 2)
void lm_head_hmma(const __half* __restrict__ A2,
                  const __half* __restrict__ B2,
                  float* __restrict__ out)
{
    extern __shared__ char smem[];
    const uint32_t sbase = smem_to_u32(smem);

    const int tid = threadIdx.x;
    const int lane = tid & 31;
    const int wid = tid >> 5;
    const int m0 = blockIdx.x * 128;
    const int n0 = blockIdx.y * 128;
    const int wm = (wid >> 2) * 64;
    const int wn = (wid & 3) * 32;

    const int lg = lane >> 3, lr = lane & 7;
    const int row16 = ((lg & 1) << 3) + lr;
    const int csel  = lg >> 1;

    float acc[4][4][4];
#pragma unroll
    for (int i = 0; i < 4; i++)
#pragma unroll
        for (int j = 0; j < 4; j++)
#pragma unroll
            for (int k = 0; k < 4; k++) acc[i][j][k] = 0.f;

    auto issue = [&](int kt) {
        const uint32_t stage = sbase + (kt & 1) * LM_STAGE_B;
#pragma unroll
        for (int i = 0; i < 4; i++) {
            int q = i * 256 + tid;
            int row = q >> 3, c = q & 7;
            uint32_t soff = row * 128 + (((uint32_t)(c ^ (row & 7))) << 4);
            cp16(stage + soff,
                 A2 + (size_t)(m0 + row) * HID + kt * LM_BK + c * 8);
            cp16(stage + LM_TILE_B + soff,
                 B2 + (size_t)(n0 + row) * HID + kt * LM_BK + c * 8);
        }
        asm volatile("cp.async.commit_group;" ::: "memory");
    };

    issue(0);

    for (int kt = 0; kt < LM_NT; kt++) {
        if (kt + 1 < LM_NT) {
            issue(kt + 1);
            asm volatile("cp.async.wait_group 1;" ::: "memory");
        } else {
            asm volatile("cp.async.wait_group 0;" ::: "memory");
        }
        __syncthreads();

        const uint32_t Ab = sbase + (kt & 1) * LM_STAGE_B;
        const uint32_t Bb = Ab + LM_TILE_B;

#pragma unroll
        for (int ks = 0; ks < 4; ks++) {
            const int kc = ks * 2;
            uint32_t a[4][4];
#pragma unroll
            for (int mt = 0; mt < 4; mt++) {
                int row = wm + mt * 16 + row16;
                uint32_t addr = Ab + row * 128 +
                    (((uint32_t)((kc + csel) ^ (row & 7))) << 4);
                asm volatile(
                    "ldmatrix.sync.aligned.m8n8.x4.shared.b16 {%0,%1,%2,%3}, [%4];"
                    : "=r"(a[mt][0]), "=r"(a[mt][1]), "=r"(a[mt][2]), "=r"(a[mt][3])
                    : "r"(addr));
            }
            uint32_t bf[4][2];
#pragma unroll
            for (int np = 0; np < 2; np++) {
                int row = wn + np * 16 + row16;
                uint32_t addr = Bb + row * 128 +
                    (((uint32_t)((kc + csel) ^ (row & 7))) << 4);
                uint32_t q0, q1, q2, q3;
                asm volatile(
                    "ldmatrix.sync.aligned.m8n8.x4.shared.b16 {%0,%1,%2,%3}, [%4];"
                    : "=r"(q0), "=r"(q1), "=r"(q2), "=r"(q3)
                    : "r"(addr));
                bf[np * 2][0] = q0;     bf[np * 2][1] = q2;
                bf[np * 2 + 1][0] = q1; bf[np * 2 + 1][1] = q3;
            }
#pragma unroll
            for (int mt = 0; mt < 4; mt++)
#pragma unroll
                for (int nt = 0; nt < 4; nt++) {
                    asm volatile(
                        "mma.sync.aligned.m16n8k16.row.col.f32.f16.f16.f32 "
                        "{%0,%1,%2,%3}, {%4,%5,%6,%7}, {%8,%9}, {%0,%1,%2,%3};"
                        : "+f"(acc[mt][nt][0]), "+f"(acc[mt][nt][1]),
                          "+f"(acc[mt][nt][2]), "+f"(acc[mt][nt][3])
                        : "r"(a[mt][0]), "r"(a[mt][1]), "r"(a[mt][2]), "r"(a[mt][3]),
                          "r"(bf[nt][0]), "r"(bf[nt][1]));
                }
        }
        __syncthreads();
    }

    const int elr = lane >> 2;
    const int elc = (lane & 3) * 2;
    const bool full = (n0 + 128 <= VOCAB);
#pragma unroll
    for (int mt = 0; mt < 4; mt++) {
#pragma unroll
        for (int nt = 0; nt < 4; nt++) {
            int gr = m0 + wm + mt * 16 + elr;
            int gc = n0 + wn + nt * 8 + elc;
            float* p0 = out + (size_t)gr * VOCAB + gc;
            float* p1 = out + (size_t)(gr + 8) * VOCAB + gc;
            if (full) {
                p0[0] = acc[mt][nt][0]; p0[1] = acc[mt][nt][1];
                p1[0] = acc[mt][nt][2]; p1[1] = acc[mt][nt][3];
            } else {
                if (gc < VOCAB)     { p0[0] = acc[mt][nt][0]; p1[0] = acc[mt][nt][2]; }
                if (gc + 1 < VOCAB) { p0[1] = acc[mt][nt][1]; p1[1] = acc[mt][nt][3]; }
            }
        }
    }
}

// ---------------------------------------------------------------------------
// Launch
// ---------------------------------------------------------------------------
extern "C" void kernel_launch(void* const* d_in, const int* in_sizes, int n_in,
                              void* d_out, int out_size)
{
    const int*   ids   = (const int*)  d_in[0];
    const float* embed = (const float*)d_in[1];
    const float* W_ih  = (const float*)d_in[2];
    const float* b_ih  = (const float*)d_in[3];
    const float* W_hh  = (const float*)d_in[4];
    const float* b_hh  = (const float*)d_in[5];
    const float* W_out = (const float*)d_in[6];
    float* out = (float*)d_out;

    float* gx_ptr;
    __half *a2_ptr, *b2_ptr;
    void* flags_ptr;
    cudaGetSymbolAddress((void**)&gx_ptr, g_gx);
    cudaGetSymbolAddress((void**)&a2_ptr, g_a2);
    cudaGetSymbolAddress((void**)&b2_ptr, g_b2);
    cudaGetSymbolAddress(&flags_ptr, g_flags);

    cudaFuncSetAttribute(lm_head_hmma,
                         cudaFuncAttributeMaxDynamicSharedMemorySize, LM_SMEM);

    // reset barrier flags (graph-capturable memset node)
    cudaMemsetAsync(flags_ptr, 0, sizeof(int) * 16 * 32);

    // 0) B2 = fp16(W_out)
    {
        int nthreads = NPAD * 64;
        conv_w1<<<(nthreads + 255) / 256, 256>>>(W_out, b2_ptr);
    }

    // 1) gx = embed[ids] @ W_ih^T + b_ih
    {
        dim3 grid(GATES / 128, MTOK / 128);
        gemm_tn<true, true><<<grid, 256>>>(embed, ids, W_ih, b_ih,
                                           gx_ptr, MTOK, GATES, DMODEL);
    }

    // 2) GRU scan v6 (16 groups x 8 CTAs)
    gru_scan6<<<128, GRU_T>>>(gx_ptr, W_hh, b_hh, a2_ptr);

    // 3) LM head on HMMA fp16 (single-term, K=256)
    {
        dim3 grid(MTOK / 128, NPAD / 128);
        lm_head_hmma<<<grid, 256, LM_SMEM>>>(a2_ptr, b2_ptr, out);
    }
}